// round 1
// baseline (speedup 1.0000x reference)
#include <cuda_runtime.h>
#include <math.h>

// Problem constants (fixed by the dataset)
#define MAXN 50000
#define MAXE 100000
#define MAXG 4096

// ---------------- device scratch (no runtime allocation allowed) ----------
__device__ float g_h[MAXN * 64];     // node hidden state (out == h)
__device__ float g_agg[MAXN * 64];   // per-step message accumulator
__device__ float g_rdeg[MAXN];       // 1/max(deg,1)
__device__ float g_cnt[MAXG];        // per-graph node counts

__device__ __forceinline__ float sigmoidf_(float x) { return 1.0f / (1.0f + expf(-x)); }
__device__ __forceinline__ float leakyf_(float x)   { return x > 0.0f ? x : 0.01f * x; }

// ---------------- degree -------------------------------------------------
__global__ void deg_kernel(const int* __restrict__ ei, float* __restrict__ deg, int E) {
    int e = blockIdx.x * blockDim.x + threadIdx.x;
    if (e < E) atomicAdd(&deg[ei[E + e]], 1.0f);
}
__global__ void rdeg_kernel(float* deg, int n) {
    int i = blockIdx.x * blockDim.x + threadIdx.x;
    if (i < n) deg[i] = 1.0f / fmaxf(deg[i], 1.0f);
}

// ---------------- init MLP: h0 = (leaky([xe,vec] @ w1^T + b1)) @ w2^T + b2 -
// Persistent blocks; 512 threads; tile = 64 nodes; thread (j = tid&63) handles
// 8 nodes (row = tid>>6) at output column j. Weights transposed in smem so
// lane reads are conflict-free; operand reads are warp-broadcast.
__global__ void __launch_bounds__(512) init_kernel(
    const int* __restrict__ x, const int* __restrict__ batch,
    const float* __restrict__ vec, const float* __restrict__ blockemb,
    const float* __restrict__ w1, const float* __restrict__ b1,
    const float* __restrict__ w2, const float* __restrict__ b2,
    float* __restrict__ h, int n)
{
    extern __shared__ float sm[];
    float* w1T   = sm;                 // [128][65]
    float* w2T   = w1T + 128 * 65;     // [64][65]
    float* in_sh = w2T + 64 * 65;      // [128][65]  layout [k][node]
    float* o1_sh = in_sh + 128 * 65;   // [64][65]   layout [k][node]
    float* b1s   = o1_sh + 64 * 65;    // 64
    float* b2s   = b1s + 64;           // 64
    int*   xi    = (int*)(b2s + 64);   // 64
    int*   bi    = xi + 64;            // 64

    const int tid = threadIdx.x;
    const int j   = tid & 63;
    const int nb  = (tid >> 6) << 3;   // first of this thread's 8 nodes

    for (int i = tid; i < 64 * 128; i += 512) { int jj = i >> 7, k = i & 127; w1T[k * 65 + jj] = w1[i]; }
    for (int i = tid; i < 64 * 64;  i += 512) { int jj = i >> 6, k = i & 63;  w2T[k * 65 + jj] = w2[i]; }
    if (tid < 64) { b1s[tid] = b1[tid]; b2s[tid] = b2[tid]; }
    __syncthreads();

    const int ntiles = (n + 63) >> 6;
    for (int tile = blockIdx.x; tile < ntiles; tile += gridDim.x) {
        const int n0 = tile << 6;
        if (tid < 64) {
            int g = n0 + tid;
            xi[tid] = (g < n) ? x[g] : 0;
            bi[tid] = (g < n) ? batch[g] : 0;
        }
        __syncthreads();
        for (int i = tid; i < 64 * 128; i += 512) {
            int nn2 = i >> 7, k = i & 127;
            float v = (k < 64) ? blockemb[xi[nn2] * 64 + k]
                               : vec[bi[nn2] * 64 + (k - 64)];
            in_sh[k * 65 + nn2] = v;
        }
        __syncthreads();

        float acc[8];
        #pragma unroll
        for (int t = 0; t < 8; t++) acc[t] = 0.0f;
        #pragma unroll 4
        for (int k = 0; k < 128; k++) {
            float w = w1T[k * 65 + j];
            #pragma unroll
            for (int t = 0; t < 8; t++) acc[t] += in_sh[k * 65 + nb + t] * w;
        }
        #pragma unroll
        for (int t = 0; t < 8; t++) o1_sh[j * 65 + nb + t] = leakyf_(acc[t] + b1s[j]);
        __syncthreads();

        #pragma unroll
        for (int t = 0; t < 8; t++) acc[t] = 0.0f;
        #pragma unroll 4
        for (int k = 0; k < 64; k++) {
            float w = w2T[k * 65 + j];
            #pragma unroll
            for (int t = 0; t < 8; t++) acc[t] += o1_sh[k * 65 + nb + t] * w;
        }
        #pragma unroll
        for (int t = 0; t < 8; t++) {
            int g = n0 + nb + t;
            if (g < n) h[(size_t)g * 64 + j] = acc[t] + b2s[j];
        }
        __syncthreads();
    }
}

// ---------------- edge kernel: msg = (h[src]·ea0) * ea1, scatter-add @ dst -
__global__ void edge_kernel(const int* __restrict__ ei, const int* __restrict__ ea,
                            const float* __restrict__ bond, const float* __restrict__ h,
                            float* __restrict__ agg, int E)
{
    int w    = (blockIdx.x * blockDim.x + threadIdx.x) >> 5;
    int lane = threadIdx.x & 31;
    if (w >= E) return;
    int src = ei[w], dst = ei[E + w];
    int a0  = ea[2 * w], a1 = ea[2 * w + 1];
    const float* hs = h + (size_t)src * 64;
    const float* e0 = bond + a0 * 64;
    float s = hs[lane] * e0[lane] + hs[lane + 32] * e0[lane + 32];
    #pragma unroll
    for (int o = 16; o; o >>= 1) s += __shfl_xor_sync(0xffffffffu, s, o);
    const float* e1 = bond + a1 * 64;
    float* ap = agg + (size_t)dst * 64;
    atomicAdd(ap + lane,      s * e1[lane]);
    atomicAdd(ap + lane + 32, s * e1[lane + 32]);
}

// ---------------- node kernel: m = leaky(agg/deg + h@root + cb); GRU step ---
__global__ void __launch_bounds__(512) node_kernel(
    const float* __restrict__ agg, const float* __restrict__ rdeg,
    float* __restrict__ h,
    const float* __restrict__ root, const float* __restrict__ cb,
    const float* __restrict__ wih, const float* __restrict__ whh,
    const float* __restrict__ bih, const float* __restrict__ bhh, int n)
{
    extern __shared__ float sm[];
    float* root_s = sm;                  // [64][65]  (k-major, as stored)
    float* wih_s  = root_s + 64 * 65;    // [64][193] transposed [k][j]
    float* whh_s  = wih_s + 64 * 193;    // [64][193]
    float* h_sh   = whh_s + 64 * 193;    // [64][65]  layout [k][node]
    float* m_sh   = h_sh + 64 * 65;      // [64][65]  layout [k][node]
    float* cb_s   = m_sh + 64 * 65;      // 64
    float* bih_s  = cb_s + 64;           // 192
    float* bhh_s  = bih_s + 192;         // 192

    const int tid = threadIdx.x;
    const int j   = tid & 63;
    const int nb  = (tid >> 6) << 3;

    for (int i = tid; i < 64 * 64; i += 512)  { int k = i >> 6, jj = i & 63; root_s[k * 65 + jj] = root[i]; }
    for (int i = tid; i < 192 * 64; i += 512) {
        int jj = i >> 6, k = i & 63;
        wih_s[k * 193 + jj] = wih[i];
        whh_s[k * 193 + jj] = whh[i];
    }
    if (tid < 64)  cb_s[tid] = cb[tid];
    if (tid < 192) { bih_s[tid] = bih[tid]; bhh_s[tid] = bhh[tid]; }
    __syncthreads();

    const int ntiles = (n + 63) >> 6;
    for (int tile = blockIdx.x; tile < ntiles; tile += gridDim.x) {
        const int n0 = tile << 6;
        for (int i = tid; i < 64 * 64; i += 512) {
            int nn2 = i >> 6, k = i & 63;
            int g = n0 + nn2;
            h_sh[k * 65 + nn2] = (g < n) ? h[(size_t)g * 64 + k] : 0.0f;
        }
        __syncthreads();

        // phase A: m = leaky(agg*rdeg + h@root + cb)
        float ma[8];
        #pragma unroll
        for (int t = 0; t < 8; t++) ma[t] = 0.0f;
        #pragma unroll 4
        for (int k = 0; k < 64; k++) {
            float rv = root_s[k * 65 + j];
            #pragma unroll
            for (int t = 0; t < 8; t++) ma[t] += h_sh[k * 65 + nb + t] * rv;
        }
        #pragma unroll
        for (int t = 0; t < 8; t++) {
            int g = n0 + nb + t;
            float a = (g < n) ? agg[(size_t)g * 64 + j] * rdeg[g] : 0.0f;
            m_sh[j * 65 + nb + t] = leakyf_(ma[t] + a + cb_s[j]);
        }
        __syncthreads();

        // phase B: 6 gate accumulators x 8 nodes
        float gir[8], giz[8], gin[8], ghr[8], ghz[8], ghn[8];
        #pragma unroll
        for (int t = 0; t < 8; t++) { gir[t] = giz[t] = gin[t] = ghr[t] = ghz[t] = ghn[t] = 0.0f; }
        #pragma unroll 2
        for (int k = 0; k < 64; k++) {
            float wr = wih_s[k * 193 + j];
            float wz = wih_s[k * 193 + 64 + j];
            float wn = wih_s[k * 193 + 128 + j];
            float vr = whh_s[k * 193 + j];
            float vz = whh_s[k * 193 + 64 + j];
            float vn = whh_s[k * 193 + 128 + j];
            #pragma unroll
            for (int t = 0; t < 8; t++) {
                float mv = m_sh[k * 65 + nb + t];
                float hv = h_sh[k * 65 + nb + t];
                gir[t] += mv * wr; giz[t] += mv * wz; gin[t] += mv * wn;
                ghr[t] += hv * vr; ghz[t] += hv * vz; ghn[t] += hv * vn;
            }
        }
        const float br  = bih_s[j] + bhh_s[j];
        const float bz  = bih_s[64 + j] + bhh_s[64 + j];
        const float bni = bih_s[128 + j];
        const float bnh = bhh_s[128 + j];
        #pragma unroll
        for (int t = 0; t < 8; t++) {
            int g = n0 + nb + t;
            if (g < n) {
                float hold = h_sh[j * 65 + nb + t];
                float r  = sigmoidf_(gir[t] + ghr[t] + br);
                float z  = sigmoidf_(giz[t] + ghz[t] + bz);
                float nn = tanhf(gin[t] + bni + r * (ghn[t] + bnh));
                h[(size_t)g * 64 + j] = (1.0f - z) * nn + z * hold;
            }
        }
        __syncthreads();
    }
}

// ---------------- pooling -------------------------------------------------
__global__ void pool_kernel(const float* __restrict__ h, const int* __restrict__ batch,
                            float* __restrict__ out, float* __restrict__ cnt, int n)
{
    int i = blockIdx.x * blockDim.x + threadIdx.x;
    if (i < n * 64) {
        int nn = i >> 6, c = i & 63;
        int g = batch[nn];
        atomicAdd(&out[g * 64 + c], h[i]);
        if (c == 0) atomicAdd(&cnt[g], 1.0f);
    }
}
__global__ void div_kernel(float* out, const float* __restrict__ cnt, int total)
{
    int i = blockIdx.x * blockDim.x + threadIdx.x;
    if (i < total) out[i] /= fmaxf(cnt[i >> 6], 1.0f);
}

// ---------------- launch --------------------------------------------------
extern "C" void kernel_launch(void* const* d_in, const int* in_sizes, int n_in,
                              void* d_out, int out_size)
{
    const int*   x        = (const int*)d_in[0];
    const int*   ei       = (const int*)d_in[1];
    const int*   ea       = (const int*)d_in[2];
    const int*   batch    = (const int*)d_in[3];
    const float* vec      = (const float*)d_in[4];
    const float* blockemb = (const float*)d_in[5];
    const float* bondemb  = (const float*)d_in[6];
    const float* w1       = (const float*)d_in[7];
    const float* b1       = (const float*)d_in[8];
    const float* w2       = (const float*)d_in[9];
    const float* b2       = (const float*)d_in[10];
    const float* root     = (const float*)d_in[11];
    const float* cb       = (const float*)d_in[12];
    const float* wih      = (const float*)d_in[13];
    const float* whh      = (const float*)d_in[14];
    const float* bih      = (const float*)d_in[15];
    const float* bhh      = (const float*)d_in[16];

    const int n = in_sizes[0];
    const int E = in_sizes[1] / 2;
    const int G = in_sizes[4] / 64;

    float *h_p, *agg_p, *rdeg_p, *cnt_p;
    cudaGetSymbolAddress((void**)&h_p,    g_h);
    cudaGetSymbolAddress((void**)&agg_p,  g_agg);
    cudaGetSymbolAddress((void**)&rdeg_p, g_rdeg);
    cudaGetSymbolAddress((void**)&cnt_p,  g_cnt);

    const size_t INIT_SMEM = (size_t)(128 * 65 + 64 * 65 + 128 * 65 + 64 * 65 + 128) * 4 + 128 * 4;
    const size_t NODE_SMEM = (size_t)(64 * 65 + 2 * 64 * 193 + 2 * 64 * 65 + 64 + 192 + 192) * 4;

    cudaFuncSetAttribute(init_kernel, cudaFuncAttributeMaxDynamicSharedMemorySize, (int)INIT_SMEM);
    cudaFuncSetAttribute(node_kernel, cudaFuncAttributeMaxDynamicSharedMemorySize, (int)NODE_SMEM);

    cudaMemsetAsync(rdeg_p, 0, (size_t)n * sizeof(float));
    cudaMemsetAsync(cnt_p,  0, (size_t)G * sizeof(float));
    cudaMemsetAsync(d_out,  0, (size_t)out_size * sizeof(float));

    deg_kernel<<<(E + 255) / 256, 256>>>(ei, rdeg_p, E);
    rdeg_kernel<<<(n + 255) / 256, 256>>>(rdeg_p, n);

    init_kernel<<<148, 512, INIT_SMEM>>>(x, batch, vec, blockemb, w1, b1, w2, b2, h_p, n);

    for (int s = 0; s < 4; s++) {
        cudaMemsetAsync(agg_p, 0, (size_t)n * 64 * sizeof(float));
        edge_kernel<<<(E * 32 + 255) / 256, 256>>>(ei, ea, bondemb, h_p, agg_p, E);
        node_kernel<<<148, 512, NODE_SMEM>>>(agg_p, rdeg_p, h_p, root, cb, wih, whh, bih, bhh, n);
    }

    pool_kernel<<<(n * 64 + 255) / 256, 256>>>(h_p, batch, (float*)d_out, cnt_p, n);
    div_kernel<<<(G * 64 + 255) / 256, 256>>>((float*)d_out, cnt_p, G * 64);
}

// round 2
// speedup vs baseline: 1.1998x; 1.1998x over previous
#include <cuda_runtime.h>
#include <math.h>

#define MAXN 50000
#define MAXE 100000
#define MAXG 4096

typedef unsigned long long ull;

// ---------------- device scratch -------------------------------------------
__device__ float g_h[MAXN * 64];
__device__ float g_agg[MAXN * 64];
__device__ float g_rdeg[MAXN];
__device__ float g_cnt[MAXG];

__device__ __forceinline__ float sigmoidf_(float x) { return 1.0f / (1.0f + expf(-x)); }
__device__ __forceinline__ float leakyf_(float x)   { return x > 0.0f ? x : 0.01f * x; }

// packed f32x2 helpers (FFMA2 — ptxas never auto-fuses; PTX-only path)
__device__ __forceinline__ void fma2(ull& d, ull a, ull b) {
    asm("fma.rn.f32x2 %0, %1, %2, %0;" : "+l"(d) : "l"(a), "l"(b));
}
__device__ __forceinline__ ull pack2(float x) {
    ull r; asm("mov.b64 %0, {%1, %1};" : "=l"(r) : "f"(x)); return r;
}
__device__ __forceinline__ float2 unpack2(ull v) {
    float2 f; asm("mov.b64 {%0, %1}, %2;" : "=f"(f.x), "=f"(f.y) : "l"(v)); return f;
}

// ---------------- degree ----------------------------------------------------
__global__ void deg_kernel(const int* __restrict__ ei, float* __restrict__ deg, int E) {
    int e = blockIdx.x * blockDim.x + threadIdx.x;
    if (e < E) atomicAdd(&deg[ei[E + e]], 1.0f);
}
__global__ void rdeg_kernel(float* deg, int n) {
    int i = blockIdx.x * blockDim.x + threadIdx.x;
    if (i < n) deg[i] = 1.0f / fmaxf(deg[i], 1.0f);
}

// ---------------- init MLP --------------------------------------------------
// 512 thr; tile = 64 nodes; thread = column j x 8 nodes (4 packed pairs).
__global__ void __launch_bounds__(512) init_kernel(
    const int* __restrict__ x, const int* __restrict__ batch,
    const float* __restrict__ vec, const float* __restrict__ blockemb,
    const float* __restrict__ w1, const float* __restrict__ b1,
    const float* __restrict__ w2, const float* __restrict__ b2,
    float* __restrict__ h, int n)
{
    extern __shared__ float sm[];
    float* w1T   = sm;                  // [128][65] (odd stride: conflict-free STS, scalar LDS)
    float* w2T   = w1T + 128 * 65;      // [64][65]
    float* in_sh = w2T + 64 * 65;       // [128][66] even stride for LDS.64, offset even
    float* o1_sh = in_sh + 128 * 66;    // [64][66]
    float* b1s   = o1_sh + 64 * 66;
    float* b2s   = b1s + 64;
    int*   xi    = (int*)(b2s + 64);
    int*   bi    = xi + 64;

    const int tid = threadIdx.x;
    const int j   = tid & 63;
    const int nb  = (tid >> 6) << 3;

    for (int i = tid; i < 64 * 128; i += 512) { int jj = i >> 7, k = i & 127; w1T[k * 65 + jj] = w1[i]; }
    for (int i = tid; i < 64 * 64;  i += 512) { int jj = i >> 6, k = i & 63;  w2T[k * 65 + jj] = w2[i]; }
    if (tid < 64) { b1s[tid] = b1[tid]; b2s[tid] = b2[tid]; }
    __syncthreads();

    const int ntiles = (n + 63) >> 6;
    for (int tile = blockIdx.x; tile < ntiles; tile += gridDim.x) {
        const int n0 = tile << 6;
        if (tid < 64) {
            int g = n0 + tid;
            xi[tid] = (g < n) ? x[g] : 0;
            bi[tid] = (g < n) ? batch[g] : 0;
        }
        __syncthreads();
        for (int i = tid; i < 64 * 128; i += 512) {
            int nn2 = i >> 7, k = i & 127;
            float v = (k < 64) ? blockemb[xi[nn2] * 64 + k]
                               : vec[bi[nn2] * 64 + (k - 64)];
            in_sh[k * 66 + nn2] = v;
        }
        __syncthreads();

        ull acc[4] = {0ull, 0ull, 0ull, 0ull};
        #pragma unroll 4
        for (int k = 0; k < 128; k++) {
            ull wp = pack2(w1T[k * 65 + j]);
            const ull* op = (const ull*)&in_sh[k * 66 + nb];
            #pragma unroll
            for (int p = 0; p < 4; p++) fma2(acc[p], op[p], wp);
        }
        {
            float bj = b1s[j];
            #pragma unroll
            for (int p = 0; p < 4; p++) {
                float2 v = unpack2(acc[p]);
                v.x = leakyf_(v.x + bj); v.y = leakyf_(v.y + bj);
                o1_sh[j * 66 + nb + 2 * p]     = v.x;
                o1_sh[j * 66 + nb + 2 * p + 1] = v.y;
            }
        }
        __syncthreads();

        ull acc2[4] = {0ull, 0ull, 0ull, 0ull};
        #pragma unroll 4
        for (int k = 0; k < 64; k++) {
            ull wp = pack2(w2T[k * 65 + j]);
            const ull* op = (const ull*)&o1_sh[k * 66 + nb];
            #pragma unroll
            for (int p = 0; p < 4; p++) fma2(acc2[p], op[p], wp);
        }
        {
            float bj = b2s[j];
            #pragma unroll
            for (int p = 0; p < 4; p++) {
                float2 v = unpack2(acc2[p]);
                int g0 = n0 + nb + 2 * p;
                if (g0 < n)     h[(size_t)g0 * 64 + j]       = v.x + bj;
                if (g0 + 1 < n) h[(size_t)(g0 + 1) * 64 + j] = v.y + bj;
            }
        }
        __syncthreads();
    }
}

// ---------------- edge kernel: agg[dst] += rdeg[dst] * (h[src]·e0) * e1 -----
__global__ void edge_kernel(const int* __restrict__ ei, const int* __restrict__ ea,
                            const float* __restrict__ bond, const float* __restrict__ h,
                            const float* __restrict__ rdeg,
                            float* __restrict__ agg, int E)
{
    int w    = (blockIdx.x * blockDim.x + threadIdx.x) >> 5;
    int lane = threadIdx.x & 31;
    if (w >= E) return;
    int src = ei[w], dst = ei[E + w];
    int a0  = ea[2 * w], a1 = ea[2 * w + 1];
    const float* hs = h + (size_t)src * 64;
    const float* e0 = bond + a0 * 64;
    float s = hs[lane] * e0[lane] + hs[lane + 32] * e0[lane + 32];
    #pragma unroll
    for (int o = 16; o; o >>= 1) s += __shfl_xor_sync(0xffffffffu, s, o);
    s *= __ldg(&rdeg[dst]);
    const float* e1 = bond + a1 * 64;
    float* ap = agg + (size_t)dst * 64;
    atomicAdd(ap + lane,      s * e1[lane]);
    atomicAdd(ap + lane + 32, s * e1[lane + 32]);
}

// ---------------- node kernel: m = leaky(agg + h@root + cb); GRU step -------
__global__ void __launch_bounds__(512) node_kernel(
    const float* __restrict__ agg,
    float* __restrict__ h,
    const float* __restrict__ root, const float* __restrict__ cb,
    const float* __restrict__ wih, const float* __restrict__ whh,
    const float* __restrict__ bih, const float* __restrict__ bhh, int n)
{
    extern __shared__ float sm[];
    float* root_s = sm;                  // [64][64] direct copy (k-major)
    float* wih_s  = root_s + 64 * 64;    // [64][193] transposed [k][gate*64+j]
    float* whh_s  = wih_s + 64 * 193;
    float* h_sh   = whh_s + 64 * 193;    // [64][66] even stride, even offset
    float* m_sh   = h_sh + 64 * 66;      // [64][66]
    float* cb_s   = m_sh + 64 * 66;
    float* bih_s  = cb_s + 64;           // 192
    float* bhh_s  = bih_s + 192;         // 192

    const int tid = threadIdx.x;
    const int j   = tid & 63;
    const int nb  = (tid >> 6) << 3;

    for (int i = tid; i < 64 * 64; i += 512)  root_s[i] = root[i];
    for (int i = tid; i < 192 * 64; i += 512) {
        int g = i >> 6, k = i & 63;
        wih_s[k * 193 + g] = wih[i];
        whh_s[k * 193 + g] = whh[i];
    }
    if (tid < 64)  cb_s[tid] = cb[tid];
    if (tid < 192) { bih_s[tid] = bih[tid]; bhh_s[tid] = bhh[tid]; }
    __syncthreads();

    const int ntiles = (n + 63) >> 6;
    for (int tile = blockIdx.x; tile < ntiles; tile += gridDim.x) {
        const int n0 = tile << 6;
        for (int i = tid; i < 64 * 64; i += 512) {
            int nn2 = i >> 6, k = i & 63;
            int g = n0 + nn2;
            h_sh[k * 66 + nn2] = (g < n) ? h[(size_t)g * 64 + k] : 0.0f;
        }
        __syncthreads();

        // phase A: m = leaky(agg + h@root + cb)   (agg already /deg)
        {
            ull ma[4] = {0ull, 0ull, 0ull, 0ull};
            #pragma unroll 4
            for (int k = 0; k < 64; k++) {
                ull rp = pack2(root_s[k * 64 + j]);
                const ull* hp = (const ull*)&h_sh[k * 66 + nb];
                #pragma unroll
                for (int p = 0; p < 4; p++) fma2(ma[p], hp[p], rp);
            }
            float cj = cb_s[j];
            #pragma unroll
            for (int p = 0; p < 4; p++) {
                float2 v = unpack2(ma[p]);
                int g0 = n0 + nb + 2 * p;
                float a0 = (g0 < n)     ? agg[(size_t)g0 * 64 + j]       : 0.0f;
                float a1 = (g0 + 1 < n) ? agg[(size_t)(g0 + 1) * 64 + j] : 0.0f;
                m_sh[j * 66 + nb + 2 * p]     = leakyf_(v.x + a0 + cj);
                m_sh[j * 66 + nb + 2 * p + 1] = leakyf_(v.y + a1 + cj);
            }
        }
        __syncthreads();

        // phase B: 6 gates x 4 node-pairs, packed FFMA2
        ull gir[4] = {0,0,0,0}, giz[4] = {0,0,0,0}, gin[4] = {0,0,0,0};
        ull ghr[4] = {0,0,0,0}, ghz[4] = {0,0,0,0}, ghn[4] = {0,0,0,0};
        #pragma unroll 2
        for (int k = 0; k < 64; k++) {
            ull wr = pack2(wih_s[k * 193 + j]);
            ull wz = pack2(wih_s[k * 193 + 64 + j]);
            ull wn = pack2(wih_s[k * 193 + 128 + j]);
            ull vr = pack2(whh_s[k * 193 + j]);
            ull vz = pack2(whh_s[k * 193 + 64 + j]);
            ull vn = pack2(whh_s[k * 193 + 128 + j]);
            const ull* mp = (const ull*)&m_sh[k * 66 + nb];
            const ull* hp = (const ull*)&h_sh[k * 66 + nb];
            #pragma unroll
            for (int p = 0; p < 4; p++) {
                ull mv = mp[p], hv = hp[p];
                fma2(gir[p], mv, wr); fma2(giz[p], mv, wz); fma2(gin[p], mv, wn);
                fma2(ghr[p], hv, vr); fma2(ghz[p], hv, vz); fma2(ghn[p], hv, vn);
            }
        }
        const float br  = bih_s[j] + bhh_s[j];
        const float bz  = bih_s[64 + j] + bhh_s[64 + j];
        const float bni = bih_s[128 + j];
        const float bnh = bhh_s[128 + j];
        #pragma unroll
        for (int p = 0; p < 4; p++) {
            float2 fir = unpack2(gir[p]), fiz = unpack2(giz[p]), fin = unpack2(gin[p]);
            float2 fhr = unpack2(ghr[p]), fhz = unpack2(ghz[p]), fhn = unpack2(ghn[p]);
            int g0 = n0 + nb + 2 * p;
            if (g0 < n) {
                float hold = h_sh[j * 66 + nb + 2 * p];
                float r  = sigmoidf_(fir.x + fhr.x + br);
                float z  = sigmoidf_(fiz.x + fhz.x + bz);
                float nn = tanhf(fin.x + bni + r * (fhn.x + bnh));
                h[(size_t)g0 * 64 + j] = (1.0f - z) * nn + z * hold;
            }
            if (g0 + 1 < n) {
                float hold = h_sh[j * 66 + nb + 2 * p + 1];
                float r  = sigmoidf_(fir.y + fhr.y + br);
                float z  = sigmoidf_(fiz.y + fhz.y + bz);
                float nn = tanhf(fin.y + bni + r * (fhn.y + bnh));
                h[(size_t)(g0 + 1) * 64 + j] = (1.0f - z) * nn + z * hold;
            }
        }
        __syncthreads();
    }
}

// ---------------- pooling ---------------------------------------------------
__global__ void pool_kernel(const float* __restrict__ h, const int* __restrict__ batch,
                            float* __restrict__ out, float* __restrict__ cnt, int n)
{
    int i = blockIdx.x * blockDim.x + threadIdx.x;
    if (i < n * 64) {
        int nn = i >> 6, c = i & 63;
        int g = batch[nn];
        atomicAdd(&out[g * 64 + c], h[i]);
        if (c == 0) atomicAdd(&cnt[g], 1.0f);
    }
}
__global__ void div_kernel(float* out, const float* __restrict__ cnt, int total)
{
    int i = blockIdx.x * blockDim.x + threadIdx.x;
    if (i < total) out[i] /= fmaxf(cnt[i >> 6], 1.0f);
}

// ---------------- launch -----------------------------------------------------
extern "C" void kernel_launch(void* const* d_in, const int* in_sizes, int n_in,
                              void* d_out, int out_size)
{
    const int*   x        = (const int*)d_in[0];
    const int*   ei       = (const int*)d_in[1];
    const int*   ea       = (const int*)d_in[2];
    const int*   batch    = (const int*)d_in[3];
    const float* vec      = (const float*)d_in[4];
    const float* blockemb = (const float*)d_in[5];
    const float* bondemb  = (const float*)d_in[6];
    const float* w1       = (const float*)d_in[7];
    const float* b1       = (const float*)d_in[8];
    const float* w2       = (const float*)d_in[9];
    const float* b2       = (const float*)d_in[10];
    const float* root     = (const float*)d_in[11];
    const float* cb       = (const float*)d_in[12];
    const float* wih      = (const float*)d_in[13];
    const float* whh      = (const float*)d_in[14];
    const float* bih      = (const float*)d_in[15];
    const float* bhh      = (const float*)d_in[16];

    const int n = in_sizes[0];
    const int E = in_sizes[1] / 2;
    const int G = in_sizes[4] / 64;

    float *h_p, *agg_p, *rdeg_p, *cnt_p;
    cudaGetSymbolAddress((void**)&h_p,    g_h);
    cudaGetSymbolAddress((void**)&agg_p,  g_agg);
    cudaGetSymbolAddress((void**)&rdeg_p, g_rdeg);
    cudaGetSymbolAddress((void**)&cnt_p,  g_cnt);

    const size_t INIT_SMEM = (size_t)(128 * 65 + 64 * 65 + 128 * 66 + 64 * 66 + 64 + 64 + 64 + 64) * 4;
    const size_t NODE_SMEM = (size_t)(64 * 64 + 2 * 64 * 193 + 2 * 64 * 66 + 64 + 192 + 192) * 4;

    cudaFuncSetAttribute(init_kernel, cudaFuncAttributeMaxDynamicSharedMemorySize, (int)INIT_SMEM);
    cudaFuncSetAttribute(node_kernel, cudaFuncAttributeMaxDynamicSharedMemorySize, (int)NODE_SMEM);

    cudaMemsetAsync(rdeg_p, 0, (size_t)n * sizeof(float));
    cudaMemsetAsync(cnt_p,  0, (size_t)G * sizeof(float));
    cudaMemsetAsync(d_out,  0, (size_t)out_size * sizeof(float));

    deg_kernel<<<(E + 255) / 256, 256>>>(ei, rdeg_p, E);
    rdeg_kernel<<<(n + 255) / 256, 256>>>(rdeg_p, n);

    init_kernel<<<148, 512, INIT_SMEM>>>(x, batch, vec, blockemb, w1, b1, w2, b2, h_p, n);

    for (int s = 0; s < 4; s++) {
        cudaMemsetAsync(agg_p, 0, (size_t)n * 64 * sizeof(float));
        edge_kernel<<<(E * 32 + 255) / 256, 256>>>(ei, ea, bondemb, h_p, rdeg_p, agg_p, E);
        node_kernel<<<148, 512, NODE_SMEM>>>(agg_p, h_p, root, cb, wih, whh, bih, bhh, n);
    }

    pool_kernel<<<(n * 64 + 255) / 256, 256>>>(h_p, batch, (float*)d_out, cnt_p, n);
    div_kernel<<<(G * 64 + 255) / 256, 256>>>((float*)d_out, cnt_p, G * 64);
}

// round 5
// speedup vs baseline: 1.7828x; 1.4859x over previous
#include <cuda_runtime.h>
#include <math.h>
#include <stdint.h>

#define MAXN 50000
#define MAXE 100000
#define MAXG 4096

typedef unsigned long long ull;

// single extern shared symbol for the whole TU
extern __shared__ __align__(1024) char smem_raw[];

// ---------------- device scratch -------------------------------------------
__device__ float g_h[MAXN * 64];
__device__ float g_agg[MAXN * 64];
__device__ float g_rdeg[MAXN];
__device__ float g_cnt[MAXG];

__device__ __forceinline__ float sigf_(float x)   { return 1.0f / (1.0f + __expf(-x)); }
__device__ __forceinline__ float tanhf_(float x)  { return 2.0f * sigf_(2.0f * x) - 1.0f; }
__device__ __forceinline__ float leakyf_(float x) { return x > 0.0f ? x : 0.01f * x; }

__device__ __forceinline__ uint32_t tf32_(float x) {
    uint32_t r; asm("cvt.rna.tf32.f32 %0, %1;" : "=r"(r) : "f"(x)); return r;
}

// m16n8k8 tf32 MMA (portable PTX, valid on compute_100)
__device__ __forceinline__ void mma8(float* c, const uint32_t* a, ull b) {
    uint32_t b0 = (uint32_t)b, b1 = (uint32_t)(b >> 32);
    asm volatile(
        "mma.sync.aligned.m16n8k8.row.col.f32.tf32.tf32.f32 "
        "{%0,%1,%2,%3}, {%4,%5,%6,%7}, {%8,%9}, {%0,%1,%2,%3};"
        : "+f"(c[0]), "+f"(c[1]), "+f"(c[2]), "+f"(c[3])
        : "r"(a[0]), "r"(a[1]), "r"(a[2]), "r"(a[3]), "r"(b0), "r"(b1));
}

// k-permutation: features (q, q+4) stored at positions (2q, 2q+1) within each 8-group
__device__ __forceinline__ int pos_(int f) {
    return (f & ~7) | ((f & 3) << 1) | ((f >> 2) & 1);
}

// load A fragment (4 regs) for rows (arow, arow+8), k-quad kq, from permuted fp32 smem
__device__ __forceinline__ void load_afrag(uint32_t* a, const ull* base, int arow, int kq) {
    ull p0 = base[arow * 33 + kq];
    ull p1 = base[(arow + 8) * 33 + kq];
    a[0] = tf32_(__uint_as_float((uint32_t)p0));
    a[2] = tf32_(__uint_as_float((uint32_t)(p0 >> 32)));
    a[1] = tf32_(__uint_as_float((uint32_t)p1));
    a[3] = tf32_(__uint_as_float((uint32_t)(p1 >> 32)));
}

// packed weight array ids
#define A_ROOT 0
#define A_IHR  1
#define A_HHR  2
#define A_IHZ  3
#define A_HHZ  4
#define A_IHN  5
#define A_HHN  6
// floats: 7 packed arrays (2048 ull each) + h_sh + m_sh + 5 bias arrays
#define PK_FLOATS   (7 * 4096)
#define HSH_OFF     PK_FLOATS
#define MSH_OFF     (HSH_OFF + 128 * 66)
#define BIAS_OFF    (MSH_OFF + 128 * 66)
#define NODE_SMEM   ((BIAS_OFF + 5 * 64) * 4)

// ---------------- degree ----------------------------------------------------
__global__ void deg_kernel(const int* __restrict__ ei, float* __restrict__ deg, int E) {
    int e = blockIdx.x * blockDim.x + threadIdx.x;
    if (e < E) atomicAdd(&deg[ei[E + e]], 1.0f);
}
__global__ void rdeg_kernel(float* deg, int n) {
    int i = blockIdx.x * blockDim.x + threadIdx.x;
    if (i < n) deg[i] = 1.0f / fmaxf(deg[i], 1.0f);
}

// ---------------- init MLP (FFMA2, from R2 — known good) --------------------
__device__ __forceinline__ void fma2(ull& d, ull a, ull b) {
    asm("fma.rn.f32x2 %0, %1, %2, %0;" : "+l"(d) : "l"(a), "l"(b));
}
__device__ __forceinline__ ull pack2(float x) {
    ull r; asm("mov.b64 %0, {%1, %1};" : "=l"(r) : "f"(x)); return r;
}
__device__ __forceinline__ float2 unpack2(ull v) {
    float2 f; asm("mov.b64 {%0, %1}, %2;" : "=f"(f.x), "=f"(f.y) : "l"(v)); return f;
}

__global__ void __launch_bounds__(512) init_kernel(
    const int* __restrict__ x, const int* __restrict__ batch,
    const float* __restrict__ vec, const float* __restrict__ blockemb,
    const float* __restrict__ w1, const float* __restrict__ b1,
    const float* __restrict__ w2, const float* __restrict__ b2,
    float* __restrict__ h, int n)
{
    float* sm = (float*)smem_raw;
    float* w1T   = sm;
    float* w2T   = w1T + 128 * 65;
    float* in_sh = w2T + 64 * 65;
    float* o1_sh = in_sh + 128 * 66;
    float* b1s   = o1_sh + 64 * 66;
    float* b2s   = b1s + 64;
    int*   xi    = (int*)(b2s + 64);
    int*   bi    = xi + 64;

    const int tid = threadIdx.x;
    const int j   = tid & 63;
    const int nb  = (tid >> 6) << 3;

    for (int i = tid; i < 64 * 128; i += 512) { int jj = i >> 7, k = i & 127; w1T[k * 65 + jj] = w1[i]; }
    for (int i = tid; i < 64 * 64;  i += 512) { int jj = i >> 6, k = i & 63;  w2T[k * 65 + jj] = w2[i]; }
    if (tid < 64) { b1s[tid] = b1[tid]; b2s[tid] = b2[tid]; }
    __syncthreads();

    const int ntiles = (n + 63) >> 6;
    for (int tile = blockIdx.x; tile < ntiles; tile += gridDim.x) {
        const int n0 = tile << 6;
        if (tid < 64) {
            int g = n0 + tid;
            xi[tid] = (g < n) ? x[g] : 0;
            bi[tid] = (g < n) ? batch[g] : 0;
        }
        __syncthreads();
        for (int i = tid; i < 64 * 128; i += 512) {
            int nn2 = i >> 7, k = i & 127;
            float v = (k < 64) ? blockemb[xi[nn2] * 64 + k] : vec[bi[nn2] * 64 + (k - 64)];
            in_sh[k * 66 + nn2] = v;
        }
        __syncthreads();

        ull acc[4] = {0ull, 0ull, 0ull, 0ull};
        #pragma unroll 4
        for (int k = 0; k < 128; k++) {
            ull wp = pack2(w1T[k * 65 + j]);
            const ull* op = (const ull*)&in_sh[k * 66 + nb];
            #pragma unroll
            for (int p = 0; p < 4; p++) fma2(acc[p], op[p], wp);
        }
        {
            float bj = b1s[j];
            #pragma unroll
            for (int p = 0; p < 4; p++) {
                float2 v = unpack2(acc[p]);
                o1_sh[j * 66 + nb + 2 * p]     = leakyf_(v.x + bj);
                o1_sh[j * 66 + nb + 2 * p + 1] = leakyf_(v.y + bj);
            }
        }
        __syncthreads();

        ull acc2[4] = {0ull, 0ull, 0ull, 0ull};
        #pragma unroll 4
        for (int k = 0; k < 64; k++) {
            ull wp = pack2(w2T[k * 65 + j]);
            const ull* op = (const ull*)&o1_sh[k * 66 + nb];
            #pragma unroll
            for (int p = 0; p < 4; p++) fma2(acc2[p], op[p], wp);
        }
        {
            float bj = b2s[j];
            #pragma unroll
            for (int p = 0; p < 4; p++) {
                float2 v = unpack2(acc2[p]);
                int g0 = n0 + nb + 2 * p;
                if (g0 < n)     h[(size_t)g0 * 64 + j]       = v.x + bj;
                if (g0 + 1 < n) h[(size_t)(g0 + 1) * 64 + j] = v.y + bj;
            }
        }
        __syncthreads();
    }
}

// ---------------- edge kernel ------------------------------------------------
__global__ void edge_kernel(const int* __restrict__ ei, const int* __restrict__ ea,
                            const float* __restrict__ bond, const float* __restrict__ h,
                            const float* __restrict__ rdeg,
                            float* __restrict__ agg, int E)
{
    int w    = (blockIdx.x * blockDim.x + threadIdx.x) >> 5;
    int lane = threadIdx.x & 31;
    if (w >= E) return;
    int src = ei[w], dst = ei[E + w];
    int a0  = ea[2 * w], a1 = ea[2 * w + 1];
    const float* hs = h + (size_t)src * 64;
    const float* e0 = bond + a0 * 64;
    float s = hs[lane] * e0[lane] + hs[lane + 32] * e0[lane + 32];
    #pragma unroll
    for (int o = 16; o; o >>= 1) s += __shfl_xor_sync(0xffffffffu, s, o);
    s *= __ldg(&rdeg[dst]);
    const float* e1 = bond + a1 * 64;
    float* ap = agg + (size_t)dst * 64;
    atomicAdd(ap + lane,      s * e1[lane]);
    atomicAdd(ap + lane + 32, s * e1[lane + 32]);
}

// ---------------- node kernel: warp-level tf32 mma.sync -----------------------
__global__ void __launch_bounds__(512, 1) node_mma(
    const float* __restrict__ agg,
    float* __restrict__ h,
    const float* __restrict__ root, const float* __restrict__ cb,
    const float* __restrict__ wih, const float* __restrict__ whh,
    const float* __restrict__ bih, const float* __restrict__ bhh, int n)
{
    float* sm   = (float*)smem_raw;
    ull*   pk   = (ull*)sm;                    // [7][2][4][8][32] packed B fragments
    float* h_sh = sm + HSH_OFF;                // [128][66], permuted k columns, fp32
    float* m_sh = sm + MSH_OFF;                // [128][66]
    float* br_s  = sm + BIAS_OFF;
    float* bz_s  = br_s + 64;
    float* bin_s = bz_s + 64;
    float* bhn_s = bin_s + 64;
    float* cb_s  = bhn_s + 64;

    const int tid  = threadIdx.x;
    const int w    = tid >> 5;
    const int lane = tid & 31;
    const int r0   = (w & 7) * 16;
    const int n0   = (w >> 3) * 32;   // feature-column half
    const int half = w >> 3;

    // ---- one-time: pack weight fragments (tf32, fragment order) ----
    for (int i = tid; i < 7 * 2048; i += 512) {
        int arr = i >> 11, rem = i & 2047;
        int hf = rem >> 10, nt = (rem >> 8) & 3, kk = (rem >> 5) & 7, ln = rem & 31;
        int k0 = kk * 8 + (ln & 3), k1 = k0 + 4;
        int nn = hf * 32 + nt * 8 + (ln >> 2);
        float w0, w1;
        switch (arr) {
            case A_ROOT: w0 = root[k0 * 64 + nn];        w1 = root[k1 * 64 + nn];        break;
            case A_IHR:  w0 = wih[nn * 64 + k0];          w1 = wih[nn * 64 + k1];          break;
            case A_HHR:  w0 = whh[nn * 64 + k0];          w1 = whh[nn * 64 + k1];          break;
            case A_IHZ:  w0 = wih[(64 + nn) * 64 + k0];   w1 = wih[(64 + nn) * 64 + k1];   break;
            case A_HHZ:  w0 = whh[(64 + nn) * 64 + k0];   w1 = whh[(64 + nn) * 64 + k1];   break;
            case A_IHN:  w0 = wih[(128 + nn) * 64 + k0];  w1 = wih[(128 + nn) * 64 + k1];  break;
            default:     w0 = whh[(128 + nn) * 64 + k0];  w1 = whh[(128 + nn) * 64 + k1];  break;
        }
        pk[i] = (ull)tf32_(w0) | ((ull)tf32_(w1) << 32);
    }
    if (tid < 64) {
        br_s[tid]  = bih[tid]       + bhh[tid];
        bz_s[tid]  = bih[64 + tid]  + bhh[64 + tid];
        bin_s[tid] = bih[128 + tid];
        bhn_s[tid] = bhh[128 + tid];
        cb_s[tid]  = cb[tid];
    }
    __syncthreads();

    const ull* hq = (const ull*)h_sh;
    const ull* mq = (const ull*)m_sh;
    const int arow = r0 + (lane >> 2);

    const int ntiles = (n + 127) >> 7;
    for (int tile = blockIdx.x; tile < ntiles; tile += gridDim.x) {
        const int nb0 = tile << 7;

        // ---- load H tile -> permuted fp32 smem ----
        {
            int row = tid >> 2, cbase = (tid & 3) * 16, gr = nb0 + row;
            float v[16];
            if (gr < n) {
                const float4* p = (const float4*)(h + (size_t)gr * 64 + cbase);
                #pragma unroll
                for (int c = 0; c < 4; c++) { float4 q = p[c]; v[4*c] = q.x; v[4*c+1] = q.y; v[4*c+2] = q.z; v[4*c+3] = q.w; }
            } else {
                #pragma unroll
                for (int t = 0; t < 16; t++) v[t] = 0.0f;
            }
            float* hr = h_sh + row * 66;
            #pragma unroll
            for (int t = 0; t < 16; t++) hr[pos_(cbase + t)] = v[t];
        }
        __syncthreads();

        // ---- GEMM1: R = H @ root (per-warp 16x32 strip) ----
        float racc[16];
        #pragma unroll
        for (int t = 0; t < 16; t++) racc[t] = 0.0f;
        #pragma unroll
        for (int kk = 0; kk < 8; kk++) {
            uint32_t a[4];
            load_afrag(a, hq, arow, kk * 4 + (lane & 3));
            #pragma unroll
            for (int nt = 0; nt < 4; nt++)
                mma8(racc + nt * 4, a, pk[A_ROOT * 2048 + half * 1024 + nt * 256 + kk * 32 + lane]);
        }
        // epilogue A: M = leaky(R + agg + cb) -> permuted m_sh
        #pragma unroll
        for (int nt = 0; nt < 4; nt++) {
            int colb = n0 + nt * 8 + (lane & 3) * 2;
            float cb0 = cb_s[colb], cb1 = cb_s[colb + 1];
            #pragma unroll
            for (int p = 0; p < 2; p++) {
                int row = arow + p * 8, gr = nb0 + row;
                float a0 = 0.0f, a1 = 0.0f;
                if (gr < n) {
                    float2 ag = *(const float2*)(agg + (size_t)gr * 64 + colb);
                    a0 = ag.x; a1 = ag.y;
                }
                m_sh[row * 66 + pos_(colb)]     = leakyf_(racc[nt * 4 + p * 2]     + a0 + cb0);
                m_sh[row * 66 + pos_(colb + 1)] = leakyf_(racc[nt * 4 + p * 2 + 1] + a1 + cb1);
            }
        }
        __syncthreads();

        // ---- GEMM2: gates (r,z accumulate M@Wih + H@Whh; in from M; hn from H) ----
        float rg[16], zg[16], ig[16], hg[16];
        #pragma unroll
        for (int t = 0; t < 16; t++) { rg[t] = zg[t] = ig[t] = hg[t] = 0.0f; }
        #pragma unroll
        for (int kk = 0; kk < 8; kk++) {
            uint32_t aM[4], aH[4];
            int kq = kk * 4 + (lane & 3);
            load_afrag(aM, mq, arow, kq);
            load_afrag(aH, hq, arow, kq);
            int pkb = half * 1024 + kk * 32 + lane;
            #pragma unroll
            for (int nt = 0; nt < 4; nt++) {
                int o = pkb + nt * 256;
                mma8(rg + nt * 4, aM, pk[A_IHR * 2048 + o]);
                mma8(rg + nt * 4, aH, pk[A_HHR * 2048 + o]);
                mma8(zg + nt * 4, aM, pk[A_IHZ * 2048 + o]);
                mma8(zg + nt * 4, aH, pk[A_HHZ * 2048 + o]);
                mma8(ig + nt * 4, aM, pk[A_IHN * 2048 + o]);
                mma8(hg + nt * 4, aH, pk[A_HHN * 2048 + o]);
            }
        }

        // ---- epilogue B: GRU gate math, write h ----
        #pragma unroll
        for (int nt = 0; nt < 4; nt++) {
            int colb = n0 + nt * 8 + (lane & 3) * 2;
            float br0 = br_s[colb], br1 = br_s[colb + 1];
            float bz0 = bz_s[colb], bz1 = bz_s[colb + 1];
            float bi0 = bin_s[colb], bi1 = bin_s[colb + 1];
            float bh0 = bhn_s[colb], bh1 = bhn_s[colb + 1];
            int p0c = pos_(colb), p1c = pos_(colb + 1);
            #pragma unroll
            for (int p = 0; p < 2; p++) {
                int row = arow + p * 8, gr = nb0 + row;
                if (gr < n) {
                    int idx = nt * 4 + p * 2;
                    float ho0 = h_sh[row * 66 + p0c];
                    float ho1 = h_sh[row * 66 + p1c];
                    float r0v = sigf_(rg[idx]     + br0);
                    float r1v = sigf_(rg[idx + 1] + br1);
                    float z0v = sigf_(zg[idx]     + bz0);
                    float z1v = sigf_(zg[idx + 1] + bz1);
                    float n0v = tanhf_(ig[idx]     + bi0 + r0v * (hg[idx]     + bh0));
                    float n1v = tanhf_(ig[idx + 1] + bi1 + r1v * (hg[idx + 1] + bh1));
                    float2 o;
                    o.x = (1.0f - z0v) * n0v + z0v * ho0;
                    o.y = (1.0f - z1v) * n1v + z1v * ho1;
                    *(float2*)(h + (size_t)gr * 64 + colb) = o;
                }
            }
        }
        __syncthreads();
    }
}

// ---------------- pooling ----------------------------------------------------
__global__ void pool_kernel(const float* __restrict__ h, const int* __restrict__ batch,
                            float* __restrict__ out, float* __restrict__ cnt, int n)
{
    int i = blockIdx.x * blockDim.x + threadIdx.x;
    if (i < n * 64) {
        int nn = i >> 6, c = i & 63;
        int g = batch[nn];
        atomicAdd(&out[g * 64 + c], h[i]);
        if (c == 0) atomicAdd(&cnt[g], 1.0f);
    }
}
__global__ void div_kernel(float* out, const float* __restrict__ cnt, int total)
{
    int i = blockIdx.x * blockDim.x + threadIdx.x;
    if (i < total) out[i] /= fmaxf(cnt[i >> 6], 1.0f);
}

// ---------------- launch ------------------------------------------------------
extern "C" void kernel_launch(void* const* d_in, const int* in_sizes, int n_in,
                              void* d_out, int out_size)
{
    const int*   x        = (const int*)d_in[0];
    const int*   ei       = (const int*)d_in[1];
    const int*   ea       = (const int*)d_in[2];
    const int*   batch    = (const int*)d_in[3];
    const float* vec      = (const float*)d_in[4];
    const float* blockemb = (const float*)d_in[5];
    const float* bondemb  = (const float*)d_in[6];
    const float* w1       = (const float*)d_in[7];
    const float* b1       = (const float*)d_in[8];
    const float* w2       = (const float*)d_in[9];
    const float* b2       = (const float*)d_in[10];
    const float* root     = (const float*)d_in[11];
    const float* cb       = (const float*)d_in[12];
    const float* wih      = (const float*)d_in[13];
    const float* whh      = (const float*)d_in[14];
    const float* bih      = (const float*)d_in[15];
    const float* bhh      = (const float*)d_in[16];

    const int n = in_sizes[0];
    const int E = in_sizes[1] / 2;
    const int G = in_sizes[4] / 64;

    float *h_p, *agg_p, *rdeg_p, *cnt_p;
    cudaGetSymbolAddress((void**)&h_p,    g_h);
    cudaGetSymbolAddress((void**)&agg_p,  g_agg);
    cudaGetSymbolAddress((void**)&rdeg_p, g_rdeg);
    cudaGetSymbolAddress((void**)&cnt_p,  g_cnt);

    const size_t INIT_SMEM = (size_t)(128 * 65 + 64 * 65 + 128 * 66 + 64 * 66 + 64 + 64 + 64 + 64) * 4;

    cudaFuncSetAttribute(init_kernel, cudaFuncAttributeMaxDynamicSharedMemorySize, (int)INIT_SMEM);
    cudaFuncSetAttribute(node_mma, cudaFuncAttributeMaxDynamicSharedMemorySize, NODE_SMEM);

    cudaMemsetAsync(rdeg_p, 0, (size_t)n * sizeof(float));
    cudaMemsetAsync(cnt_p,  0, (size_t)G * sizeof(float));
    cudaMemsetAsync(d_out,  0, (size_t)out_size * sizeof(float));

    deg_kernel<<<(E + 255) / 256, 256>>>(ei, rdeg_p, E);
    rdeg_kernel<<<(n + 255) / 256, 256>>>(rdeg_p, n);

    init_kernel<<<148, 512, INIT_SMEM>>>(x, batch, vec, blockemb, w1, b1, w2, b2, h_p, n);

    for (int s = 0; s < 4; s++) {
        cudaMemsetAsync(agg_p, 0, (size_t)n * 64 * sizeof(float));
        edge_kernel<<<(E * 32 + 255) / 256, 256>>>(ei, ea, bondemb, h_p, rdeg_p, agg_p, E);
        node_mma<<<148, 512, NODE_SMEM>>>(agg_p, h_p, root, cb, wih, whh, bih, bhh, n);
    }

    pool_kernel<<<(n * 64 + 255) / 256, 256>>>(h_p, batch, (float*)d_out, cnt_p, n);
    div_kernel<<<(G * 64 + 255) / 256, 256>>>((float*)d_out, cnt_p, G * 64);
}

// round 6
// speedup vs baseline: 2.0745x; 1.1636x over previous
#include <cuda_runtime.h>
#include <math.h>
#include <stdint.h>

#define MAXN 50000
#define MAXE 100000
#define MAXG 4096

typedef unsigned long long ull;

extern __shared__ __align__(1024) char smem_raw[];

// ---------------- device scratch -------------------------------------------
__device__ float g_h[MAXN * 64];
__device__ float g_agg[MAXN * 64];
__device__ float g_rdeg[MAXN];
__device__ float g_cnt[MAXG];

__device__ __forceinline__ float sigf_(float x)   { return 1.0f / (1.0f + __expf(-x)); }
__device__ __forceinline__ float tanhf_(float x)  { return 2.0f * sigf_(2.0f * x) - 1.0f; }
__device__ __forceinline__ float leakyf_(float x) { return x > 0.0f ? x : 0.01f * x; }

__device__ __forceinline__ uint32_t tf32_(float x) {
    uint32_t r; asm("cvt.rna.tf32.f32 %0, %1;" : "=r"(r) : "f"(x)); return r;
}

// m16n8k8 tf32 MMA (portable PTX)
__device__ __forceinline__ void mma8(float* c, const uint32_t* a, ull b) {
    uint32_t b0 = (uint32_t)b, b1 = (uint32_t)(b >> 32);
    asm volatile(
        "mma.sync.aligned.m16n8k8.row.col.f32.tf32.tf32.f32 "
        "{%0,%1,%2,%3}, {%4,%5,%6,%7}, {%8,%9}, {%0,%1,%2,%3};"
        : "+f"(c[0]), "+f"(c[1]), "+f"(c[2]), "+f"(c[3])
        : "r"(a[0]), "r"(a[1]), "r"(a[2]), "r"(a[3]), "r"(b0), "r"(b1));
}

// k-permutation: features (q, q+4) stored at positions (2q, 2q+1) within each 8-group
__device__ __forceinline__ int pos_(int f) {
    return (f & ~7) | ((f & 3) << 1) | ((f >> 2) & 1);
}

// load A fragment (4 regs) from tf32-stored smem; strideq in ull units
__device__ __forceinline__ void load_afrag2(uint32_t* a, const ull* base, int arow, int kq, int strideq) {
    ull p0 = base[arow * strideq + kq];
    ull p1 = base[(arow + 8) * strideq + kq];
    a[0] = (uint32_t)p0; a[2] = (uint32_t)(p0 >> 32);
    a[1] = (uint32_t)p1; a[3] = (uint32_t)(p1 >> 32);
}

// node kernel packed weight ids
#define A_ROOT 0
#define A_IHR  1
#define A_HHR  2
#define A_IHZ  3
#define A_HHZ  4
#define A_IHN  5
#define A_HHN  6
#define PK_FLOATS   (7 * 4096)
#define BIAS_OFF    (PK_FLOATS + 2 * 128 * 66)
#define NODE_SMEM   ((BIAS_OFF + 5 * 64) * 4)

// init kernel smem (float units)
#define INIT_SMEM_F 37760
#define INIT_SMEM   (INIT_SMEM_F * 4)

// ---------------- degree ----------------------------------------------------
__global__ void deg_kernel(const int* __restrict__ ei, float* __restrict__ deg, int E) {
    int e = blockIdx.x * blockDim.x + threadIdx.x;
    if (e < E) atomicAdd(&deg[ei[E + e]], 1.0f);
}
__global__ void rdeg_kernel(float* deg, int n) {
    int i = blockIdx.x * blockDim.x + threadIdx.x;
    if (i < n) deg[i] = 1.0f / fmaxf(deg[i], 1.0f);
}

// ---------------- init MLP: mma.sync tf32 ------------------------------------
__global__ void __launch_bounds__(512, 1) init_mma(
    const int* __restrict__ x, const int* __restrict__ batch,
    const float* __restrict__ vec, const float* __restrict__ blockemb,
    const float* __restrict__ w1, const float* __restrict__ b1,
    const float* __restrict__ w2, const float* __restrict__ b2,
    float* __restrict__ h, int n)
{
    float* smf = (float*)smem_raw;
    ull* w1pk = (ull*)smf;                          // [2][4][16][32]
    ull* w2pk = w1pk + 4096;                        // [2][4][8][32]
    uint32_t* in_u = (uint32_t*)smf + 12288;        // [128][132] tf32
    uint32_t* o1_u = (uint32_t*)smf + 29184;        // [128][66]  tf32
    float* b1s = smf + 37632;
    float* b2s = smf + 37696;

    const int tid  = threadIdx.x;
    const int w    = tid >> 5;
    const int lane = tid & 31;
    const int r0   = (w & 7) * 16;
    const int half = w >> 3;
    const int n0   = half * 32;
    const int arow = r0 + (lane >> 2);

    for (int i = tid; i < 4096; i += 512) {
        int hf = i >> 11, nt = (i >> 9) & 3, kk = (i >> 5) & 15, ln = i & 31;
        int k0 = kk * 8 + (ln & 3), nn = hf * 32 + nt * 8 + (ln >> 2);
        w1pk[i] = (ull)tf32_(w1[nn * 128 + k0]) | ((ull)tf32_(w1[nn * 128 + k0 + 4]) << 32);
    }
    for (int i = tid; i < 2048; i += 512) {
        int hf = i >> 10, nt = (i >> 8) & 3, kk = (i >> 5) & 7, ln = i & 31;
        int k0 = kk * 8 + (ln & 3), nn = hf * 32 + nt * 8 + (ln >> 2);
        w2pk[i] = (ull)tf32_(w2[nn * 64 + k0]) | ((ull)tf32_(w2[nn * 64 + k0 + 4]) << 32);
    }
    if (tid < 64) { b1s[tid] = b1[tid]; b2s[tid] = b2[tid]; }
    __syncthreads();

    const ull* inq = (const ull*)in_u;
    const ull* o1q = (const ull*)o1_u;

    const int ntiles = (n + 127) >> 7;
    for (int tile = blockIdx.x; tile < ntiles; tile += gridDim.x) {
        const int nb0 = tile << 7;

        // gather [emb | vec] -> permuted tf32 smem
        {
            int row = tid >> 2, cpart = (tid & 3) * 32, gr = nb0 + row;
            uint32_t* ir = in_u + row * 132;
            if (gr < n) {
                const float* src = (cpart < 64)
                    ? (blockemb + (size_t)x[gr] * 64 + cpart)
                    : (vec + (size_t)batch[gr] * 64 + (cpart - 64));
                #pragma unroll
                for (int c = 0; c < 8; c++) {
                    float4 q = ((const float4*)src)[c];
                    int f = cpart + c * 4;
                    ir[pos_(f)]     = tf32_(q.x);
                    ir[pos_(f + 1)] = tf32_(q.y);
                    ir[pos_(f + 2)] = tf32_(q.z);
                    ir[pos_(f + 3)] = tf32_(q.w);
                }
            } else {
                #pragma unroll
                for (int c = 0; c < 32; c++) ir[pos_(cpart + c)] = 0u;
            }
        }
        __syncthreads();

        // GEMM1: o1 = leaky(in @ w1^T + b1)
        float racc[16];
        #pragma unroll
        for (int t = 0; t < 16; t++) racc[t] = 0.0f;
        #pragma unroll
        for (int kk = 0; kk < 16; kk++) {
            uint32_t a[4];
            load_afrag2(a, inq, arow, kk * 4 + (lane & 3), 66);
            #pragma unroll
            for (int nt = 0; nt < 4; nt++)
                mma8(racc + nt * 4, a, w1pk[half * 2048 + nt * 512 + kk * 32 + lane]);
        }
        #pragma unroll
        for (int nt = 0; nt < 4; nt++) {
            int colb = n0 + nt * 8 + (lane & 3) * 2;
            float c0 = b1s[colb], c1 = b1s[colb + 1];
            #pragma unroll
            for (int p = 0; p < 2; p++) {
                int row = arow + p * 8;
                o1_u[row * 66 + pos_(colb)]     = tf32_(leakyf_(racc[nt * 4 + p * 2]     + c0));
                o1_u[row * 66 + pos_(colb + 1)] = tf32_(leakyf_(racc[nt * 4 + p * 2 + 1] + c1));
            }
        }
        __syncthreads();

        // GEMM2: h0 = o1 @ w2^T + b2
        float acc2[16];
        #pragma unroll
        for (int t = 0; t < 16; t++) acc2[t] = 0.0f;
        #pragma unroll
        for (int kk = 0; kk < 8; kk++) {
            uint32_t a[4];
            load_afrag2(a, o1q, arow, kk * 4 + (lane & 3), 33);
            #pragma unroll
            for (int nt = 0; nt < 4; nt++)
                mma8(acc2 + nt * 4, a, w2pk[half * 1024 + nt * 256 + kk * 32 + lane]);
        }
        #pragma unroll
        for (int nt = 0; nt < 4; nt++) {
            int colb = n0 + nt * 8 + (lane & 3) * 2;
            float c0 = b2s[colb], c1 = b2s[colb + 1];
            #pragma unroll
            for (int p = 0; p < 2; p++) {
                int row = arow + p * 8, gr = nb0 + row;
                if (gr < n)
                    *(float2*)(h + (size_t)gr * 64 + colb) =
                        make_float2(acc2[nt * 4 + p * 2] + c0, acc2[nt * 4 + p * 2 + 1] + c1);
            }
        }
        __syncthreads();
    }
}

// ---------------- edge kernel: half-warp/edge, vec4 reduction atomics --------
__global__ void edge_kernel(const int* __restrict__ ei, const int* __restrict__ ea,
                            const float* __restrict__ bond, const float* __restrict__ h,
                            const float* __restrict__ rdeg,
                            float* __restrict__ agg, int E)
{
    int idx = blockIdx.x * blockDim.x + threadIdx.x;
    int e = idx >> 4;
    int l = idx & 15;
    bool valid = (e < E);
    int ec = valid ? e : (E - 1);
    int src = ei[ec], dst = ei[E + ec];
    int a0  = ea[2 * ec], a1 = ea[2 * ec + 1];
    float4 hv = *(const float4*)(h + (size_t)src * 64 + 4 * l);
    float4 e0 = *(const float4*)(bond + (size_t)a0 * 64 + 4 * l);
    float s = hv.x * e0.x + hv.y * e0.y + hv.z * e0.z + hv.w * e0.w;
    #pragma unroll
    for (int o = 8; o; o >>= 1) s += __shfl_xor_sync(0xffffffffu, s, o);
    s *= __ldg(&rdeg[dst]);
    float4 ev = *(const float4*)(bond + (size_t)a1 * 64 + 4 * l);
    if (valid) {
        float* ap = agg + (size_t)dst * 64 + 4 * l;
        asm volatile("red.global.add.v4.f32 [%0], {%1,%2,%3,%4};"
                     :: "l"(ap), "f"(s * ev.x), "f"(s * ev.y), "f"(s * ev.z), "f"(s * ev.w)
                     : "memory");
    }
}

// ---------------- node kernel: mma.sync tf32, tf32-resident smem -------------
__global__ void __launch_bounds__(512, 1) node_mma(
    const float* __restrict__ agg,
    float* __restrict__ h,
    const float* __restrict__ root, const float* __restrict__ cb,
    const float* __restrict__ wih, const float* __restrict__ whh,
    const float* __restrict__ bih, const float* __restrict__ bhh, int n)
{
    float* smf = (float*)smem_raw;
    ull*   pk  = (ull*)smf;                        // 7 packed B-fragment arrays
    uint32_t* h_u = (uint32_t*)smf + PK_FLOATS;    // [128][66] tf32
    uint32_t* m_u = h_u + 128 * 66;                // [128][66] tf32
    float* br_s  = smf + BIAS_OFF;
    float* bz_s  = br_s + 64;
    float* bin_s = bz_s + 64;
    float* bhn_s = bin_s + 64;
    float* cb_s  = bhn_s + 64;

    const int tid  = threadIdx.x;
    const int w    = tid >> 5;
    const int lane = tid & 31;
    const int r0   = (w & 7) * 16;
    const int half = w >> 3;
    const int n0   = half * 32;
    const int arow = r0 + (lane >> 2);

    for (int i = tid; i < 7 * 2048; i += 512) {
        int arr = i >> 11, rem = i & 2047;
        int hf = rem >> 10, nt = (rem >> 8) & 3, kk = (rem >> 5) & 7, ln = rem & 31;
        int k0 = kk * 8 + (ln & 3), k1 = k0 + 4;
        int nn = hf * 32 + nt * 8 + (ln >> 2);
        float w0, w1;
        switch (arr) {
            case A_ROOT: w0 = root[k0 * 64 + nn];         w1 = root[k1 * 64 + nn];         break;
            case A_IHR:  w0 = wih[nn * 64 + k0];          w1 = wih[nn * 64 + k1];          break;
            case A_HHR:  w0 = whh[nn * 64 + k0];          w1 = whh[nn * 64 + k1];          break;
            case A_IHZ:  w0 = wih[(64 + nn) * 64 + k0];   w1 = wih[(64 + nn) * 64 + k1];   break;
            case A_HHZ:  w0 = whh[(64 + nn) * 64 + k0];   w1 = whh[(64 + nn) * 64 + k1];   break;
            case A_IHN:  w0 = wih[(128 + nn) * 64 + k0];  w1 = wih[(128 + nn) * 64 + k1];  break;
            default:     w0 = whh[(128 + nn) * 64 + k0];  w1 = whh[(128 + nn) * 64 + k1];  break;
        }
        pk[i] = (ull)tf32_(w0) | ((ull)tf32_(w1) << 32);
    }
    if (tid < 64) {
        br_s[tid]  = bih[tid]       + bhh[tid];
        bz_s[tid]  = bih[64 + tid]  + bhh[64 + tid];
        bin_s[tid] = bih[128 + tid];
        bhn_s[tid] = bhh[128 + tid];
        cb_s[tid]  = cb[tid];
    }
    __syncthreads();

    const ull* hq = (const ull*)h_u;
    const ull* mq = (const ull*)m_u;

    const int ntiles = (n + 127) >> 7;
    for (int tile = blockIdx.x; tile < ntiles; tile += gridDim.x) {
        const int nb0 = tile << 7;

        // ---- H tile -> permuted tf32 smem (convert once) ----
        {
            int row = tid >> 2, cbase = (tid & 3) * 16, gr = nb0 + row;
            uint32_t* hr = h_u + row * 66;
            if (gr < n) {
                const float4* p = (const float4*)(h + (size_t)gr * 64 + cbase);
                #pragma unroll
                for (int c = 0; c < 4; c++) {
                    float4 q = p[c];
                    int f = cbase + c * 4;
                    hr[pos_(f)]     = tf32_(q.x);
                    hr[pos_(f + 1)] = tf32_(q.y);
                    hr[pos_(f + 2)] = tf32_(q.z);
                    hr[pos_(f + 3)] = tf32_(q.w);
                }
            } else {
                #pragma unroll
                for (int t = 0; t < 16; t++) hr[pos_(cbase + t)] = 0u;
            }
        }
        __syncthreads();

        // prefetch agg (fp32 exact)
        float2 agf[8];
        #pragma unroll
        for (int nt = 0; nt < 4; nt++) {
            int colb = n0 + nt * 8 + (lane & 3) * 2;
            #pragma unroll
            for (int p = 0; p < 2; p++) {
                int gr = nb0 + arow + p * 8;
                agf[nt * 2 + p] = (gr < n) ? *(const float2*)(agg + (size_t)gr * 64 + colb)
                                           : make_float2(0.0f, 0.0f);
            }
        }

        // ---- GEMM1: R = H @ root ----
        float racc[16];
        #pragma unroll
        for (int t = 0; t < 16; t++) racc[t] = 0.0f;
        #pragma unroll
        for (int kk = 0; kk < 8; kk++) {
            uint32_t a[4];
            load_afrag2(a, hq, arow, kk * 4 + (lane & 3), 33);
            #pragma unroll
            for (int nt = 0; nt < 4; nt++)
                mma8(racc + nt * 4, a, pk[A_ROOT * 2048 + half * 1024 + nt * 256 + kk * 32 + lane]);
        }
        // epilogue A: M = leaky(R + agg + cb) -> tf32 smem
        #pragma unroll
        for (int nt = 0; nt < 4; nt++) {
            int colb = n0 + nt * 8 + (lane & 3) * 2;
            float cb0 = cb_s[colb], cb1 = cb_s[colb + 1];
            #pragma unroll
            for (int p = 0; p < 2; p++) {
                int row = arow + p * 8;
                float2 ag = agf[nt * 2 + p];
                m_u[row * 66 + pos_(colb)]     = tf32_(leakyf_(racc[nt * 4 + p * 2]     + ag.x + cb0));
                m_u[row * 66 + pos_(colb + 1)] = tf32_(leakyf_(racc[nt * 4 + p * 2 + 1] + ag.y + cb1));
            }
        }
        __syncthreads();

        // prefetch h_old (fp32 exact, L1/L2 hot)
        float2 hof[8];
        #pragma unroll
        for (int nt = 0; nt < 4; nt++) {
            int colb = n0 + nt * 8 + (lane & 3) * 2;
            #pragma unroll
            for (int p = 0; p < 2; p++) {
                int gr = nb0 + arow + p * 8;
                hof[nt * 2 + p] = (gr < n) ? *(const float2*)(h + (size_t)gr * 64 + colb)
                                           : make_float2(0.0f, 0.0f);
            }
        }

        // ---- GEMM2: gates ----
        float rg[16], zg[16], ig[16], hg[16];
        #pragma unroll
        for (int t = 0; t < 16; t++) { rg[t] = zg[t] = ig[t] = hg[t] = 0.0f; }
        #pragma unroll
        for (int kk = 0; kk < 8; kk++) {
            uint32_t aM[4], aH[4];
            int kq = kk * 4 + (lane & 3);
            load_afrag2(aM, mq, arow, kq, 33);
            load_afrag2(aH, hq, arow, kq, 33);
            int pkb = half * 1024 + kk * 32 + lane;
            #pragma unroll
            for (int nt = 0; nt < 4; nt++) {
                int o = pkb + nt * 256;
                mma8(rg + nt * 4, aM, pk[A_IHR * 2048 + o]);
                mma8(rg + nt * 4, aH, pk[A_HHR * 2048 + o]);
                mma8(zg + nt * 4, aM, pk[A_IHZ * 2048 + o]);
                mma8(zg + nt * 4, aH, pk[A_HHZ * 2048 + o]);
                mma8(ig + nt * 4, aM, pk[A_IHN * 2048 + o]);
                mma8(hg + nt * 4, aH, pk[A_HHN * 2048 + o]);
            }
        }

        // ---- epilogue B: GRU gate math ----
        #pragma unroll
        for (int nt = 0; nt < 4; nt++) {
            int colb = n0 + nt * 8 + (lane & 3) * 2;
            float br0 = br_s[colb], br1 = br_s[colb + 1];
            float bz0 = bz_s[colb], bz1 = bz_s[colb + 1];
            float bi0 = bin_s[colb], bi1 = bin_s[colb + 1];
            float bh0 = bhn_s[colb], bh1 = bhn_s[colb + 1];
            #pragma unroll
            for (int p = 0; p < 2; p++) {
                int gr = nb0 + arow + p * 8;
                if (gr < n) {
                    int idx = nt * 4 + p * 2;
                    float2 ho = hof[nt * 2 + p];
                    float r0v = sigf_(rg[idx]     + br0);
                    float r1v = sigf_(rg[idx + 1] + br1);
                    float z0v = sigf_(zg[idx]     + bz0);
                    float z1v = sigf_(zg[idx + 1] + bz1);
                    float n0v = tanhf_(ig[idx]     + bi0 + r0v * (hg[idx]     + bh0));
                    float n1v = tanhf_(ig[idx + 1] + bi1 + r1v * (hg[idx + 1] + bh1));
                    float2 o;
                    o.x = (1.0f - z0v) * n0v + z0v * ho.x;
                    o.y = (1.0f - z1v) * n1v + z1v * ho.y;
                    *(float2*)(h + (size_t)gr * 64 + colb) = o;
                }
            }
        }
        __syncthreads();
    }
}

// ---------------- pooling ----------------------------------------------------
__global__ void pool_kernel(const float* __restrict__ h, const int* __restrict__ batch,
                            float* __restrict__ out, float* __restrict__ cnt, int n)
{
    int i = blockIdx.x * blockDim.x + threadIdx.x;
    if (i < n * 64) {
        int nn = i >> 6, c = i & 63;
        int g = batch[nn];
        atomicAdd(&out[g * 64 + c], h[i]);
        if (c == 0) atomicAdd(&cnt[g], 1.0f);
    }
}
__global__ void div_kernel(float* out, const float* __restrict__ cnt, int total)
{
    int i = blockIdx.x * blockDim.x + threadIdx.x;
    if (i < total) out[i] /= fmaxf(cnt[i >> 6], 1.0f);
}

// ---------------- launch ------------------------------------------------------
extern "C" void kernel_launch(void* const* d_in, const int* in_sizes, int n_in,
                              void* d_out, int out_size)
{
    const int*   x        = (const int*)d_in[0];
    const int*   ei       = (const int*)d_in[1];
    const int*   ea       = (const int*)d_in[2];
    const int*   batch    = (const int*)d_in[3];
    const float* vec      = (const float*)d_in[4];
    const float* blockemb = (const float*)d_in[5];
    const float* bondemb  = (const float*)d_in[6];
    const float* w1       = (const float*)d_in[7];
    const float* b1       = (const float*)d_in[8];
    const float* w2       = (const float*)d_in[9];
    const float* b2       = (const float*)d_in[10];
    const float* root     = (const float*)d_in[11];
    const float* cb       = (const float*)d_in[12];
    const float* wih      = (const float*)d_in[13];
    const float* whh      = (const float*)d_in[14];
    const float* bih      = (const float*)d_in[15];
    const float* bhh      = (const float*)d_in[16];

    const int n = in_sizes[0];
    const int E = in_sizes[1] / 2;
    const int G = in_sizes[4] / 64;

    float *h_p, *agg_p, *rdeg_p, *cnt_p;
    cudaGetSymbolAddress((void**)&h_p,    g_h);
    cudaGetSymbolAddress((void**)&agg_p,  g_agg);
    cudaGetSymbolAddress((void**)&rdeg_p, g_rdeg);
    cudaGetSymbolAddress((void**)&cnt_p,  g_cnt);

    cudaFuncSetAttribute(init_mma, cudaFuncAttributeMaxDynamicSharedMemorySize, INIT_SMEM);
    cudaFuncSetAttribute(node_mma, cudaFuncAttributeMaxDynamicSharedMemorySize, NODE_SMEM);

    cudaMemsetAsync(rdeg_p, 0, (size_t)n * sizeof(float));
    cudaMemsetAsync(cnt_p,  0, (size_t)G * sizeof(float));
    cudaMemsetAsync(d_out,  0, (size_t)out_size * sizeof(float));

    deg_kernel<<<(E + 255) / 256, 256>>>(ei, rdeg_p, E);
    rdeg_kernel<<<(n + 255) / 256, 256>>>(rdeg_p, n);

    init_mma<<<148, 512, INIT_SMEM>>>(x, batch, vec, blockemb, w1, b1, w2, b2, h_p, n);

    for (int s = 0; s < 4; s++) {
        cudaMemsetAsync(agg_p, 0, (size_t)n * 64 * sizeof(float));
        edge_kernel<<<(E * 16 + 255) / 256, 256>>>(ei, ea, bondemb, h_p, rdeg_p, agg_p, E);
        node_mma<<<148, 512, NODE_SMEM>>>(agg_p, h_p, root, cb, wih, whh, bih, bhh, n);
    }

    pool_kernel<<<(n * 64 + 255) / 256, 256>>>(h_p, batch, (float*)d_out, cnt_p, n);
    div_kernel<<<(G * 64 + 255) / 256, 256>>>((float*)d_out, cnt_p, G * 64);
}

// round 7
// speedup vs baseline: 2.3127x; 1.1148x over previous
#include <cuda_runtime.h>
#include <math.h>
#include <stdint.h>

#define MAXN 50000
#define MAXE 100000
#define MAXG 4096

typedef unsigned long long ull;

extern __shared__ __align__(1024) char smem_raw[];

// ---------------- device scratch -------------------------------------------
__device__ float g_h[MAXN * 64];
__device__ float g_agg[MAXN * 64];   // zero-initialized at load; node_mma re-zeroes after consume
__device__ float g_rdeg[MAXN];
__device__ float g_cnt[MAXG];
__device__ ull   g_pk_node[14336];   // 7 packed B-fragment arrays (node)
__device__ ull   g_pk_init[6144];    // w1 (4096) + w2 (2048) packed
__device__ float g_bias_node[320];   // br, bz, bin, bhn, cb
__device__ float g_bias_init[128];   // b1, b2

__device__ __forceinline__ float sigf_(float x)   { return 1.0f / (1.0f + __expf(-x)); }
__device__ __forceinline__ float tanhf_(float x)  { return 2.0f * sigf_(2.0f * x) - 1.0f; }
__device__ __forceinline__ float leakyf_(float x) { return x > 0.0f ? x : 0.01f * x; }

__device__ __forceinline__ uint32_t tf32_(float x) {
    uint32_t r; asm("cvt.rna.tf32.f32 %0, %1;" : "=r"(r) : "f"(x)); return r;
}

// m16n8k8 tf32 MMA (portable PTX)
__device__ __forceinline__ void mma8(float* c, const uint32_t* a, ull b) {
    uint32_t b0 = (uint32_t)b, b1 = (uint32_t)(b >> 32);
    asm volatile(
        "mma.sync.aligned.m16n8k8.row.col.f32.tf32.tf32.f32 "
        "{%0,%1,%2,%3}, {%4,%5,%6,%7}, {%8,%9}, {%0,%1,%2,%3};"
        : "+f"(c[0]), "+f"(c[1]), "+f"(c[2]), "+f"(c[3])
        : "r"(a[0]), "r"(a[1]), "r"(a[2]), "r"(a[3]), "r"(b0), "r"(b1));
}

__device__ __forceinline__ int pos_(int f) {
    return (f & ~7) | ((f & 3) << 1) | ((f >> 2) & 1);
}

__device__ __forceinline__ void load_afrag2(uint32_t* a, const ull* base, int arow, int kq, int strideq) {
    ull p0 = base[arow * strideq + kq];
    ull p1 = base[(arow + 8) * strideq + kq];
    a[0] = (uint32_t)p0; a[2] = (uint32_t)(p0 >> 32);
    a[1] = (uint32_t)p1; a[3] = (uint32_t)(p1 >> 32);
}

// node kernel packed weight ids
#define A_ROOT 0
#define A_IHR  1
#define A_HHR  2
#define A_IHZ  3
#define A_HHZ  4
#define A_IHN  5
#define A_HHN  6
#define PK_FLOATS   (7 * 4096)
#define BIAS_OFF    (PK_FLOATS + 2 * 128 * 66)
#define NODE_SMEM   ((BIAS_OFF + 5 * 64) * 4)

#define INIT_SMEM_F 37760
#define INIT_SMEM   (INIT_SMEM_F * 4)

// ---------------- pack kernel: all weight fragments once --------------------
__global__ void pack_kernel(
    const float* __restrict__ root, const float* __restrict__ cb,
    const float* __restrict__ wih, const float* __restrict__ whh,
    const float* __restrict__ bih, const float* __restrict__ bhh,
    const float* __restrict__ w1, const float* __restrict__ b1,
    const float* __restrict__ w2, const float* __restrict__ b2)
{
    for (int i = blockIdx.x * blockDim.x + threadIdx.x; i < 21024; i += gridDim.x * blockDim.x) {
        if (i < 14336) {
            // node packed fragments
            int arr = i >> 11, rem = i & 2047;
            int hf = rem >> 10, nt = (rem >> 8) & 3, kk = (rem >> 5) & 7, ln = rem & 31;
            int k0 = kk * 8 + (ln & 3), k1 = k0 + 4;
            int nn = hf * 32 + nt * 8 + (ln >> 2);
            float w0, w1v;
            switch (arr) {
                case A_ROOT: w0 = root[k0 * 64 + nn];         w1v = root[k1 * 64 + nn];         break;
                case A_IHR:  w0 = wih[nn * 64 + k0];          w1v = wih[nn * 64 + k1];          break;
                case A_HHR:  w0 = whh[nn * 64 + k0];          w1v = whh[nn * 64 + k1];          break;
                case A_IHZ:  w0 = wih[(64 + nn) * 64 + k0];   w1v = wih[(64 + nn) * 64 + k1];   break;
                case A_HHZ:  w0 = whh[(64 + nn) * 64 + k0];   w1v = whh[(64 + nn) * 64 + k1];   break;
                case A_IHN:  w0 = wih[(128 + nn) * 64 + k0];  w1v = wih[(128 + nn) * 64 + k1];  break;
                default:     w0 = whh[(128 + nn) * 64 + k0];  w1v = whh[(128 + nn) * 64 + k1];  break;
            }
            g_pk_node[i] = (ull)tf32_(w0) | ((ull)tf32_(w1v) << 32);
        } else if (i < 18432) {
            // init w1 packed
            int j = i - 14336;
            int hf = j >> 11, nt = (j >> 9) & 3, kk = (j >> 5) & 15, ln = j & 31;
            int k0 = kk * 8 + (ln & 3), nn = hf * 32 + nt * 8 + (ln >> 2);
            g_pk_init[j] = (ull)tf32_(w1[nn * 128 + k0]) | ((ull)tf32_(w1[nn * 128 + k0 + 4]) << 32);
        } else if (i < 20480) {
            // init w2 packed
            int j = i - 18432;
            int hf = j >> 10, nt = (j >> 8) & 3, kk = (j >> 5) & 7, ln = j & 31;
            int k0 = kk * 8 + (ln & 3), nn = hf * 32 + nt * 8 + (ln >> 2);
            g_pk_init[4096 + j] = (ull)tf32_(w2[nn * 64 + k0]) | ((ull)tf32_(w2[nn * 64 + k0 + 4]) << 32);
        } else if (i < 20800) {
            int j = i - 20480;  // node biases
            float v;
            if (j < 64)       v = bih[j] + bhh[j];
            else if (j < 128) v = bih[j] + bhh[j];          // z: j in [64,128)
            else if (j < 192) v = bih[64 + j];              // bin: bih[128+t], t=j-128 -> bih[j+... ] careful
            else if (j < 256) v = bhh[j - 64];              // bhn: bhh[128+t], t=j-192
            else              v = cb[j - 256];
            // fix bin indexing explicitly
            if (j >= 128 && j < 192) v = bih[128 + (j - 128)];
            g_bias_node[j] = v;
        } else {
            int j = i - 20800;  // init biases
            g_bias_init[j] = (j < 64) ? b1[j] : b2[j - 64];
        }
    }
}

// ---------------- degree ----------------------------------------------------
__global__ void deg_kernel(const int* __restrict__ ei, float* __restrict__ deg, int E) {
    int e = blockIdx.x * blockDim.x + threadIdx.x;
    if (e < E) atomicAdd(&deg[ei[E + e]], 1.0f);
}
__global__ void rdeg_kernel(float* deg, int n) {
    int i = blockIdx.x * blockDim.x + threadIdx.x;
    if (i < n) deg[i] = 1.0f / fmaxf(deg[i], 1.0f);
}

// ---------------- init MLP: mma.sync tf32 ------------------------------------
__global__ void __launch_bounds__(512, 1) init_mma(
    const int* __restrict__ x, const int* __restrict__ batch,
    const float* __restrict__ vec, const float* __restrict__ blockemb,
    float* __restrict__ h, int n)
{
    float* smf = (float*)smem_raw;
    ull* w1pk = (ull*)smf;                          // [4096]
    ull* w2pk = w1pk + 4096;                        // [2048]
    uint32_t* in_u = (uint32_t*)smf + 12288;        // [128][132] tf32
    uint32_t* o1_u = (uint32_t*)smf + 29184;        // [128][66]  tf32
    float* b1s = smf + 37632;
    float* b2s = b1s + 64;

    const int tid  = threadIdx.x;
    const int w    = tid >> 5;
    const int lane = tid & 31;
    const int r0   = (w & 7) * 16;
    const int half = w >> 3;
    const int n0   = half * 32;
    const int arow = r0 + (lane >> 2);

    for (int i = tid; i < 6144; i += 512) w1pk[i] = g_pk_init[i];  // covers w1pk+w2pk (contiguous)
    if (tid < 128) b1s[tid] = g_bias_init[tid];
    __syncthreads();

    const ull* inq = (const ull*)in_u;
    const ull* o1q = (const ull*)o1_u;

    const int ntiles = (n + 127) >> 7;
    for (int tile = blockIdx.x; tile < ntiles; tile += gridDim.x) {
        const int nb0 = tile << 7;

        {
            int row = tid >> 2, cpart = (tid & 3) * 32, gr = nb0 + row;
            uint32_t* ir = in_u + row * 132;
            if (gr < n) {
                const float* src = (cpart < 64)
                    ? (blockemb + (size_t)x[gr] * 64 + cpart)
                    : (vec + (size_t)batch[gr] * 64 + (cpart - 64));
                #pragma unroll
                for (int c = 0; c < 8; c++) {
                    float4 q = ((const float4*)src)[c];
                    int f = cpart + c * 4;
                    ir[pos_(f)]     = tf32_(q.x);
                    ir[pos_(f + 1)] = tf32_(q.y);
                    ir[pos_(f + 2)] = tf32_(q.z);
                    ir[pos_(f + 3)] = tf32_(q.w);
                }
            } else {
                #pragma unroll
                for (int c = 0; c < 32; c++) ir[pos_(cpart + c)] = 0u;
            }
        }
        __syncthreads();

        float racc[16];
        #pragma unroll
        for (int t = 0; t < 16; t++) racc[t] = 0.0f;
        #pragma unroll
        for (int kk = 0; kk < 16; kk++) {
            uint32_t a[4];
            load_afrag2(a, inq, arow, kk * 4 + (lane & 3), 66);
            #pragma unroll
            for (int nt = 0; nt < 4; nt++)
                mma8(racc + nt * 4, a, w1pk[half * 2048 + nt * 512 + kk * 32 + lane]);
        }
        #pragma unroll
        for (int nt = 0; nt < 4; nt++) {
            int colb = n0 + nt * 8 + (lane & 3) * 2;
            float c0 = b1s[colb], c1 = b1s[colb + 1];
            #pragma unroll
            for (int p = 0; p < 2; p++) {
                int row = arow + p * 8;
                o1_u[row * 66 + pos_(colb)]     = tf32_(leakyf_(racc[nt * 4 + p * 2]     + c0));
                o1_u[row * 66 + pos_(colb + 1)] = tf32_(leakyf_(racc[nt * 4 + p * 2 + 1] + c1));
            }
        }
        __syncthreads();

        float acc2[16];
        #pragma unroll
        for (int t = 0; t < 16; t++) acc2[t] = 0.0f;
        #pragma unroll
        for (int kk = 0; kk < 8; kk++) {
            uint32_t a[4];
            load_afrag2(a, o1q, arow, kk * 4 + (lane & 3), 33);
            #pragma unroll
            for (int nt = 0; nt < 4; nt++)
                mma8(acc2 + nt * 4, a, w2pk[half * 1024 + nt * 256 + kk * 32 + lane]);
        }
        #pragma unroll
        for (int nt = 0; nt < 4; nt++) {
            int colb = n0 + nt * 8 + (lane & 3) * 2;
            float c0 = b2s[colb], c1 = b2s[colb + 1];
            #pragma unroll
            for (int p = 0; p < 2; p++) {
                int row = arow + p * 8, gr = nb0 + row;
                if (gr < n)
                    *(float2*)(h + (size_t)gr * 64 + colb) =
                        make_float2(acc2[nt * 4 + p * 2] + c0, acc2[nt * 4 + p * 2 + 1] + c1);
            }
        }
        __syncthreads();
    }
}

// ---------------- edge kernel: quarter-warp/edge, vec4 red -------------------
__global__ void edge_kernel(const int* __restrict__ ei, const int* __restrict__ ea,
                            const float* __restrict__ bond, const float* __restrict__ h,
                            const float* __restrict__ rdeg,
                            float* __restrict__ agg, int E)
{
    int idx = blockIdx.x * blockDim.x + threadIdx.x;
    int e = idx >> 4;
    int l = idx & 15;
    bool valid = (e < E);
    int ec = valid ? e : (E - 1);
    int src = ei[ec], dst = ei[E + ec];
    int a0  = ea[2 * ec], a1 = ea[2 * ec + 1];
    float4 hv = *(const float4*)(h + (size_t)src * 64 + 4 * l);
    float4 e0 = *(const float4*)(bond + (size_t)a0 * 64 + 4 * l);
    float s = hv.x * e0.x + hv.y * e0.y + hv.z * e0.z + hv.w * e0.w;
    #pragma unroll
    for (int o = 8; o; o >>= 1) s += __shfl_xor_sync(0xffffffffu, s, o);
    s *= __ldg(&rdeg[dst]);
    float4 ev = *(const float4*)(bond + (size_t)a1 * 64 + 4 * l);
    if (valid) {
        float* ap = agg + (size_t)dst * 64 + 4 * l;
        asm volatile("red.global.add.v4.f32 [%0], {%1,%2,%3,%4};"
                     :: "l"(ap), "f"(s * ev.x), "f"(s * ev.y), "f"(s * ev.z), "f"(s * ev.w)
                     : "memory");
    }
}

// ---------------- node kernel ------------------------------------------------
__global__ void __launch_bounds__(512, 1) node_mma(
    float* __restrict__ agg,
    float* __restrict__ h, int n)
{
    float* smf = (float*)smem_raw;
    ull*   pk  = (ull*)smf;
    uint32_t* h_u = (uint32_t*)smf + PK_FLOATS;
    uint32_t* m_u = h_u + 128 * 66;
    float* br_s  = smf + BIAS_OFF;
    float* bz_s  = br_s + 64;
    float* bin_s = bz_s + 64;
    float* bhn_s = bin_s + 64;
    float* cb_s  = bhn_s + 64;

    const int tid  = threadIdx.x;
    const int w    = tid >> 5;
    const int lane = tid & 31;
    const int r0   = (w & 7) * 16;
    const int half = w >> 3;
    const int n0   = half * 32;
    const int arow = r0 + (lane >> 2);

    for (int i = tid; i < 14336; i += 512) pk[i] = g_pk_node[i];
    if (tid < 320) br_s[tid] = g_bias_node[tid];
    __syncthreads();

    const ull* hq = (const ull*)h_u;
    const ull* mq = (const ull*)m_u;

    const int ntiles = (n + 127) >> 7;
    for (int tile = blockIdx.x; tile < ntiles; tile += gridDim.x) {
        const int nb0 = tile << 7;

        {
            int row = tid >> 2, cbase = (tid & 3) * 16, gr = nb0 + row;
            uint32_t* hr = h_u + row * 66;
            if (gr < n) {
                const float4* p = (const float4*)(h + (size_t)gr * 64 + cbase);
                #pragma unroll
                for (int c = 0; c < 4; c++) {
                    float4 q = p[c];
                    int f = cbase + c * 4;
                    hr[pos_(f)]     = tf32_(q.x);
                    hr[pos_(f + 1)] = tf32_(q.y);
                    hr[pos_(f + 2)] = tf32_(q.z);
                    hr[pos_(f + 3)] = tf32_(q.w);
                }
            } else {
                #pragma unroll
                for (int t = 0; t < 16; t++) hr[pos_(cbase + t)] = 0u;
            }
        }
        __syncthreads();

        // prefetch agg (fp32) then zero it for the next step
        float2 agf[8];
        #pragma unroll
        for (int nt = 0; nt < 4; nt++) {
            int colb = n0 + nt * 8 + (lane & 3) * 2;
            #pragma unroll
            for (int p = 0; p < 2; p++) {
                int gr = nb0 + arow + p * 8;
                if (gr < n) {
                    float2* ap = (float2*)(agg + (size_t)gr * 64 + colb);
                    agf[nt * 2 + p] = *ap;
                    *ap = make_float2(0.0f, 0.0f);
                } else {
                    agf[nt * 2 + p] = make_float2(0.0f, 0.0f);
                }
            }
        }

        // GEMM1: R = H @ root
        float racc[16];
        #pragma unroll
        for (int t = 0; t < 16; t++) racc[t] = 0.0f;
        #pragma unroll
        for (int kk = 0; kk < 8; kk++) {
            uint32_t a[4];
            load_afrag2(a, hq, arow, kk * 4 + (lane & 3), 33);
            #pragma unroll
            for (int nt = 0; nt < 4; nt++)
                mma8(racc + nt * 4, a, pk[A_ROOT * 2048 + half * 1024 + nt * 256 + kk * 32 + lane]);
        }
        #pragma unroll
        for (int nt = 0; nt < 4; nt++) {
            int colb = n0 + nt * 8 + (lane & 3) * 2;
            float cb0 = cb_s[colb], cb1 = cb_s[colb + 1];
            #pragma unroll
            for (int p = 0; p < 2; p++) {
                int row = arow + p * 8;
                float2 ag = agf[nt * 2 + p];
                m_u[row * 66 + pos_(colb)]     = tf32_(leakyf_(racc[nt * 4 + p * 2]     + ag.x + cb0));
                m_u[row * 66 + pos_(colb + 1)] = tf32_(leakyf_(racc[nt * 4 + p * 2 + 1] + ag.y + cb1));
            }
        }
        __syncthreads();

        // prefetch h_old (fp32)
        float2 hof[8];
        #pragma unroll
        for (int nt = 0; nt < 4; nt++) {
            int colb = n0 + nt * 8 + (lane & 3) * 2;
            #pragma unroll
            for (int p = 0; p < 2; p++) {
                int gr = nb0 + arow + p * 8;
                hof[nt * 2 + p] = (gr < n) ? *(const float2*)(h + (size_t)gr * 64 + colb)
                                           : make_float2(0.0f, 0.0f);
            }
        }

        // GEMM2: gates
        float rg[16], zg[16], ig[16], hg[16];
        #pragma unroll
        for (int t = 0; t < 16; t++) { rg[t] = zg[t] = ig[t] = hg[t] = 0.0f; }
        #pragma unroll
        for (int kk = 0; kk < 8; kk++) {
            uint32_t aM[4], aH[4];
            int kq = kk * 4 + (lane & 3);
            load_afrag2(aM, mq, arow, kq, 33);
            load_afrag2(aH, hq, arow, kq, 33);
            int pkb = half * 1024 + kk * 32 + lane;
            #pragma unroll
            for (int nt = 0; nt < 4; nt++) {
                int o = pkb + nt * 256;
                mma8(rg + nt * 4, aM, pk[A_IHR * 2048 + o]);
                mma8(rg + nt * 4, aH, pk[A_HHR * 2048 + o]);
                mma8(zg + nt * 4, aM, pk[A_IHZ * 2048 + o]);
                mma8(zg + nt * 4, aH, pk[A_HHZ * 2048 + o]);
                mma8(ig + nt * 4, aM, pk[A_IHN * 2048 + o]);
                mma8(hg + nt * 4, aH, pk[A_HHN * 2048 + o]);
            }
        }

        // epilogue B: GRU gate math
        #pragma unroll
        for (int nt = 0; nt < 4; nt++) {
            int colb = n0 + nt * 8 + (lane & 3) * 2;
            float br0 = br_s[colb], br1 = br_s[colb + 1];
            float bz0 = bz_s[colb], bz1 = bz_s[colb + 1];
            float bi0 = bin_s[colb], bi1 = bin_s[colb + 1];
            float bh0 = bhn_s[colb], bh1 = bhn_s[colb + 1];
            #pragma unroll
            for (int p = 0; p < 2; p++) {
                int gr = nb0 + arow + p * 8;
                if (gr < n) {
                    int idx = nt * 4 + p * 2;
                    float2 ho = hof[nt * 2 + p];
                    float r0v = sigf_(rg[idx]     + br0);
                    float r1v = sigf_(rg[idx + 1] + br1);
                    float z0v = sigf_(zg[idx]     + bz0);
                    float z1v = sigf_(zg[idx + 1] + bz1);
                    float n0v = tanhf_(ig[idx]     + bi0 + r0v * (hg[idx]     + bh0));
                    float n1v = tanhf_(ig[idx + 1] + bi1 + r1v * (hg[idx + 1] + bh1));
                    float2 o;
                    o.x = (1.0f - z0v) * n0v + z0v * ho.x;
                    o.y = (1.0f - z1v) * n1v + z1v * ho.y;
                    *(float2*)(h + (size_t)gr * 64 + colb) = o;
                }
            }
        }
        __syncthreads();
    }
}

// ---------------- pooling: quarter-warp red.v4 --------------------------------
__global__ void pool_kernel(const float* __restrict__ h, const int* __restrict__ batch,
                            float* __restrict__ out, float* __restrict__ cnt, int n)
{
    int idx = blockIdx.x * blockDim.x + threadIdx.x;
    int nn = idx >> 4, l = idx & 15;
    if (nn >= n) return;
    int g = batch[nn];
    float4 v = *(const float4*)(h + (size_t)nn * 64 + 4 * l);
    float* op = out + (size_t)g * 64 + 4 * l;
    asm volatile("red.global.add.v4.f32 [%0], {%1,%2,%3,%4};"
                 :: "l"(op), "f"(v.x), "f"(v.y), "f"(v.z), "f"(v.w) : "memory");
    if (l == 0) atomicAdd(&cnt[g], 1.0f);
}
__global__ void div_kernel(float* out, const float* __restrict__ cnt, int total)
{
    int i = blockIdx.x * blockDim.x + threadIdx.x;
    if (i < total) out[i] /= fmaxf(cnt[i >> 6], 1.0f);
}

// ---------------- launch ------------------------------------------------------
extern "C" void kernel_launch(void* const* d_in, const int* in_sizes, int n_in,
                              void* d_out, int out_size)
{
    const int*   x        = (const int*)d_in[0];
    const int*   ei       = (const int*)d_in[1];
    const int*   ea       = (const int*)d_in[2];
    const int*   batch    = (const int*)d_in[3];
    const float* vec      = (const float*)d_in[4];
    const float* blockemb = (const float*)d_in[5];
    const float* bondemb  = (const float*)d_in[6];
    const float* w1       = (const float*)d_in[7];
    const float* b1       = (const float*)d_in[8];
    const float* w2       = (const float*)d_in[9];
    const float* b2       = (const float*)d_in[10];
    const float* root     = (const float*)d_in[11];
    const float* cb       = (const float*)d_in[12];
    const float* wih      = (const float*)d_in[13];
    const float* whh      = (const float*)d_in[14];
    const float* bih      = (const float*)d_in[15];
    const float* bhh      = (const float*)d_in[16];

    const int n = in_sizes[0];
    const int E = in_sizes[1] / 2;
    const int G = in_sizes[4] / 64;

    float *h_p, *agg_p, *rdeg_p, *cnt_p;
    cudaGetSymbolAddress((void**)&h_p,    g_h);
    cudaGetSymbolAddress((void**)&agg_p,  g_agg);
    cudaGetSymbolAddress((void**)&rdeg_p, g_rdeg);
    cudaGetSymbolAddress((void**)&cnt_p,  g_cnt);

    cudaFuncSetAttribute(init_mma, cudaFuncAttributeMaxDynamicSharedMemorySize, INIT_SMEM);
    cudaFuncSetAttribute(node_mma, cudaFuncAttributeMaxDynamicSharedMemorySize, NODE_SMEM);

    cudaMemsetAsync(rdeg_p, 0, (size_t)n * sizeof(float));
    cudaMemsetAsync(cnt_p,  0, (size_t)G * sizeof(float));
    cudaMemsetAsync(d_out,  0, (size_t)out_size * sizeof(float));

    pack_kernel<<<42, 512>>>(root, cb, wih, whh, bih, bhh, w1, b1, w2, b2);
    deg_kernel<<<(E + 255) / 256, 256>>>(ei, rdeg_p, E);
    rdeg_kernel<<<(n + 255) / 256, 256>>>(rdeg_p, n);

    init_mma<<<148, 512, INIT_SMEM>>>(x, batch, vec, blockemb, h_p, n);

    for (int s = 0; s < 4; s++) {
        edge_kernel<<<(E * 16 + 255) / 256, 256>>>(ei, ea, bondemb, h_p, rdeg_p, agg_p, E);
        node_mma<<<148, 512, NODE_SMEM>>>(agg_p, h_p, n);
    }

    pool_kernel<<<(n * 16 + 255) / 256, 256>>>(h_p, batch, (float*)d_out, cnt_p, n);
    div_kernel<<<(G * 64 + 255) / 256, 256>>>((float*)d_out, cnt_p, G * 64);
}